// round 1
// baseline (speedup 1.0000x reference)
#include <cuda_runtime.h>
#include <math.h>

#define NB 16
#define NV 1024
#define ND 16
#define NE 64
#define NF 16
#define NH 128
#define NHD 64
#define BIGF 1e9f
#define VD (NV*ND)               // 16384 edges per batch
#define ROWS_TOTAL (NB*VD)       // 262144 edge rows

// ---------------- scratch (device globals; no allocations allowed) ----------
__device__ float g_h[(size_t)ROWS_TOTAL*NH];      // edge states (134MB)
__device__ float g_nodeenc[NB*NV*NH];             // node encodings
__device__ float g_nmpe[NB*NV*NH];                // node_msg + node_enc (per layer)
__device__ float g_enc0[NV*NH];                   // emb_norm @ W_enc[:E]
__device__ float g_nw[ROWS_TOTAL];                // decoder scalar per edge
__device__ float g_dest[ROWS_TOTAL];              // dest attention
__device__ float g_norm[ROWS_TOTAL];              // sparsemax output
__device__ float g_dualvars[NB*NV];
__device__ float g_flowcost[NB];

// ---------------- register-tiled GEMM accumulate helper ---------------------
// C[4][TN] += A(rows r4..r4+3, K wide, stride K) * W(K x NW, stride NW) cols cB..cB+TN-1
template<int K, int TN, int NW>
__device__ __forceinline__ void mm_acc(const float* __restrict__ As,
                                       const float* __restrict__ Ws,
                                       int r4, int cB, float (&acc)[4][TN]) {
#pragma unroll 4
    for (int k = 0; k < K; k++) {
        float a0 = As[(r4+0)*K + k];
        float a1 = As[(r4+1)*K + k];
        float a2 = As[(r4+2)*K + k];
        float a3 = As[(r4+3)*K + k];
#pragma unroll
        for (int jj = 0; jj < TN; jj += 4) {
            float4 wv = *(const float4*)(Ws + k*NW + cB + jj);
            float wj[4] = {wv.x, wv.y, wv.z, wv.w};
#pragma unroll
            for (int u = 0; u < 4; u++) {
                acc[0][jj+u] += a0*wj[u];
                acc[1][jj+u] += a1*wj[u];
                acc[2][jj+u] += a2*wj[u];
                acc[3][jj+u] += a3*wj[u];
            }
        }
    }
}

__device__ __forceinline__ float sigmoidf_(float x) { return 1.f/(1.f+expf(-x)); }

// ---------------- encoding --------------------------------------------------
// enc0[v][h] = (emb[v]/max(||emb[v]||,1)) . W_enc[:E, h]
extern "C" __global__ void k_enc0(const float* __restrict__ emb,
                                  const float* __restrict__ W_enc) {
    int v = blockIdx.x, t = threadIdx.x;   // 128 threads
    __shared__ float e_s[NE];
    __shared__ float red[128];
    if (t < NE) e_s[t] = emb[v*NE + t];
    __syncthreads();
    float sq = (t < NE) ? e_s[t]*e_s[t] : 0.f;
    red[t] = sq; __syncthreads();
    for (int s = 64; s > 0; s >>= 1) { if (t < s) red[t] += red[t+s]; __syncthreads(); }
    float inv = 1.f / fmaxf(sqrtf(red[0]), 1.f);
    float acc = 0.f;
    for (int k = 0; k < NE; k++) acc += e_s[k]*inv*W_enc[k*NH + t];
    g_enc0[v*NH + t] = acc;
}

// node_enc[b,v,h] = enc0[v,h] + nf[b,v,:].W_enc[E:,h] + b_enc[h]
extern "C" __global__ void k_nodeenc(const float* __restrict__ nf,
                                     const float* __restrict__ W_enc,
                                     const float* __restrict__ b_enc) {
    int bv = blockIdx.x, t = threadIdx.x;  // 128 threads
    int v = bv % NV;
    __shared__ float f_s[NF];
    if (t < NF) f_s[t] = nf[bv*NF + t];
    __syncthreads();
    float acc = g_enc0[v*NH + t] + b_enc[t];
    for (int k = 0; k < NF; k++) acc += f_s[k]*W_enc[(NE+k)*NH + t];
    g_nodeenc[bv*NH + t] = acc;
}

// h init = gather(node_enc, adj) * valid
extern "C" __global__ void k_inith(const int* __restrict__ adj,
                                   const int* __restrict__ num_nodes) {
    int row = blockIdx.x, k = threadIdx.x;
    int b = row / VD;
    int a = adj[row];
    float valid = (a == num_nodes[b]) ? 0.f : 1.f;
    int ac = min(a, NV-1);
    g_h[(size_t)row*NH + k] = valid * g_nodeenc[(b*NV + ac)*NH + k];
}

// ---------------- GAT layer: fused t/attn/node_msg, writes nmpe -------------
extern "C" __global__ void __launch_bounds__(256,1)
k_gat(const float* __restrict__ W_gat, const float* __restrict__ b_gat,
      const float* __restrict__ a_gat, const int* __restrict__ adj,
      const int* __restrict__ num_nodes) {
    extern __shared__ float sm[];
    float* W_s = sm;                 // 128*128
    float* h_s = W_s + 16384;        // 64*128 (reused for t)
    float* red = h_s + 8192;         // 64*16
    float* a_s = red + 1024;         // 128
    float* lg  = a_s + 128;          // 64
    float* at  = lg + 64;            // 64
    const int tid = threadIdx.x;
    const int r0  = blockIdx.x * 64;
    const int b   = r0 / VD;
    const int nn  = num_nodes[b];

    for (int i = tid; i < 16384; i += 256) W_s[i] = W_gat[i];
    for (int i = tid; i < 8192;  i += 256) h_s[i] = g_h[(size_t)r0*NH + i];
    if (tid < 128) a_s[tid] = a_gat[tid];
    __syncthreads();

    const int c8 = (tid & 15) * 8;
    const int r4 = (tid >> 4) * 4;
    float acc[4][8];
#pragma unroll
    for (int i = 0; i < 4; i++)
#pragma unroll
        for (int j = 0; j < 8; j++) acc[i][j] = b_gat[c8+j];
    mm_acc<128,8,128>(h_s, W_s, r4, c8, acc);
#pragma unroll
    for (int i = 0; i < 4; i++)
#pragma unroll
        for (int j = 0; j < 8; j++) acc[i][j] = tanhf(acc[i][j]);
    __syncthreads();                      // everyone done reading h_s
    // write t into h_s + partial logits
#pragma unroll
    for (int i = 0; i < 4; i++) {
        int row = r4 + i; float p = 0.f;
#pragma unroll
        for (int j = 0; j < 8; j++) {
            float tv = acc[i][j];
            h_s[row*128 + c8 + j] = tv;
            p += tv * a_s[c8+j];
        }
        red[row*16 + (tid & 15)] = p;
    }
    __syncthreads();
    if (tid < 64) {
        float s = 0.f;
#pragma unroll
        for (int c = 0; c < 16; c++) s += red[tid*16 + c];
        int a = adj[r0 + tid];
        lg[tid] = s - ((a == nn) ? BIGF : 0.f);
    }
    __syncthreads();
    if (tid < 4) {   // softmax over D per node
        float mx = -1e30f;
#pragma unroll
        for (int d = 0; d < 16; d++) mx = fmaxf(mx, lg[tid*16+d]);
        float e[16], ssum = 0.f;
#pragma unroll
        for (int d = 0; d < 16; d++) { e[d] = expf(lg[tid*16+d]-mx); ssum += e[d]; }
#pragma unroll
        for (int d = 0; d < 16; d++) at[tid*16+d] = e[d]/ssum;
    }
    __syncthreads();
    // node_msg + node_enc -> nmpe
    for (int i = tid; i < 512; i += 256) {
        int node = i >> 7, col = i & 127;
        float s = 0.f;
#pragma unroll
        for (int d = 0; d < 16; d++) s += at[node*16+d] * h_s[(node*16+d)*128 + col];
        int gn = (r0 >> 4) + node;    // global (b*V+v)
        g_nmpe[gn*NH + col] = s + g_nodeenc[gn*NH + col];
    }
}

// ---------------- fused GRU: x from gather, gx+gh GEMMs, in-place h ----------
extern "C" __global__ void __launch_bounds__(256,1)
k_gru(const float* __restrict__ Wx, const float* __restrict__ Wh,
      const float* __restrict__ bg, const int* __restrict__ adj,
      const int* __restrict__ num_nodes) {
    extern __shared__ float sm[];
    float* x_s  = sm;            // 64*128
    float* h_s  = sm + 8192;     // 64*128
    float* Wx_s = sm + 16384;    // 128*128
    float* Wh_s = sm + 32768;    // 128*128
    __shared__ int   adj_s[64];
    __shared__ float val_s[64];
    const int tid = threadIdx.x;
    const int r0  = blockIdx.x * 64;
    const int b   = r0 / VD;
    if (tid < 64) {
        int a = adj[r0 + tid];
        adj_s[tid] = min(a, NV-1);
        val_s[tid] = (a == num_nodes[b]) ? 0.f : 1.f;
    }
    __syncthreads();
    for (int i = tid; i < 8192; i += 256) {
        int row = i >> 7, k = i & 127;
        h_s[i] = g_h[(size_t)(r0+row)*NH + k];
        x_s[i] = tanhf(val_s[row] * g_nmpe[(b*NV + adj_s[row])*NH + k]);
    }
    const int c8 = (tid & 15) * 8;
    const int r4 = (tid >> 4) * 4;
    float zg[4][8], rg[4][8];
    for (int g = 0; g < 3; g++) {
        if (g > 0) __syncthreads();      // protect previous weight tiles
        for (int i = tid; i < 16384; i += 256) {
            int k = i >> 7, c = i & 127;
            Wx_s[i] = Wx[k*384 + g*128 + c];
            Wh_s[i] = Wh[k*384 + g*128 + c];
        }
        __syncthreads();
        float acc[4][8];
#pragma unroll
        for (int i = 0; i < 4; i++)
#pragma unroll
            for (int j = 0; j < 8; j++) acc[i][j] = bg[g*128 + c8 + j];
        mm_acc<128,8,128>(x_s, Wx_s, r4, c8, acc);
        if (g < 2) {
            mm_acc<128,8,128>(h_s, Wh_s, r4, c8, acc);
            if (g == 0) {
#pragma unroll
                for (int i = 0; i < 4; i++)
#pragma unroll
                    for (int j = 0; j < 8; j++) zg[i][j] = sigmoidf_(acc[i][j]);
            } else {
#pragma unroll
                for (int i = 0; i < 4; i++)
#pragma unroll
                    for (int j = 0; j < 8; j++) rg[i][j] = sigmoidf_(acc[i][j]);
            }
        } else {
            float acc2[4][8];
#pragma unroll
            for (int i = 0; i < 4; i++)
#pragma unroll
                for (int j = 0; j < 8; j++) acc2[i][j] = 0.f;
            mm_acc<128,8,128>(h_s, Wh_s, r4, c8, acc2);
#pragma unroll
            for (int i = 0; i < 4; i++) {
#pragma unroll
                for (int j = 0; j < 8; j++) {
                    float cand = tanhf(acc[i][j] + rg[i][j]*acc2[i][j]);
                    float hold = h_s[(r4+i)*128 + c8 + j];
                    acc[i][j] = zg[i][j]*hold + (1.f - zg[i][j])*cand;
                }
                size_t base = (size_t)(r0 + r4 + i)*NH + c8;
                *(float4*)(g_h + base)     = make_float4(acc[i][0],acc[i][1],acc[i][2],acc[i][3]);
                *(float4*)(g_h + base + 4) = make_float4(acc[i][4],acc[i][5],acc[i][6],acc[i][7]);
            }
        }
    }
}

// ---------------- decoder: nw per edge --------------------------------------
extern "C" __global__ void __launch_bounds__(256,1)
k_dec(const float* __restrict__ W1, const float* __restrict__ b1,
      const float* __restrict__ W2, const float* __restrict__ b2,
      const int* __restrict__ adj) {
    extern __shared__ float sm[];
    float* din  = sm;             // 64*256
    float* W1_s = sm + 16384;     // 256*64
    float* red  = sm + 32768;     // 64*16
    float* w2s  = sm + 33792;     // 64
    __shared__ int opp_s[64];
    const int tid = threadIdx.x;
    const int r0  = blockIdx.x * 64;
    const int b   = r0 / VD;
    if (tid < 64) {
        int row = r0 + tid;
        int d = row & 15;
        int a = min(adj[row], NV-1);
        opp_s[tid] = (b*NV + a)*ND + (d ^ 1);
        w2s[tid] = W2[tid];
    }
    __syncthreads();
    for (int i = tid; i < 16384; i += 256) W1_s[i] = W1[i];
    for (int i = tid; i < 16384; i += 256) {
        int row = i >> 8, k = i & 255;
        float v;
        if (k < 128) v = g_h[(size_t)(r0+row)*NH + k];
        else         v = g_h[(size_t)(r0+row)*NH + (k-128)]
                       + g_h[(size_t)opp_s[row]*NH + (k-128)];
        din[i] = v;
    }
    __syncthreads();
    const int c4 = (tid & 15) * 4;
    const int r4 = (tid >> 4) * 4;
    float acc[4][4];
#pragma unroll
    for (int i = 0; i < 4; i++)
#pragma unroll
        for (int j = 0; j < 4; j++) acc[i][j] = b1[c4+j];
    mm_acc<256,4,64>(din, W1_s, r4, c4, acc);
#pragma unroll
    for (int i = 0; i < 4; i++) {
        float p = 0.f;
#pragma unroll
        for (int j = 0; j < 4; j++) p += tanhf(acc[i][j]) * w2s[c4+j];
        red[(r4+i)*16 + (tid & 15)] = p;
    }
    __syncthreads();
    if (tid < 64) {
        float s = b2[0];
#pragma unroll
        for (int c = 0; c < 16; c++) s += red[tid*16 + c];
        g_nw[r0 + tid] = s;
    }
}

// ---------------- destination softmax over incoming edges -------------------
extern "C" __global__ void k_dest(const int* __restrict__ inv_adj,
                                  const int* __restrict__ num_nodes) {
    int bv = blockIdx.x*128 + threadIdx.x;
    if (bv >= NB*NV) return;
    int b = bv / NV;
    int nn = num_nodes[b];
    float w[16]; float mx = -1e30f;
#pragma unroll
    for (int d = 0; d < 16; d++) {
        int ia = inv_adj[bv*16 + d];
        float m = (ia == nn) ? 1.f : 0.f;
        float val = g_nw[(b*NV + min(ia, NV-1))*ND + d] - BIGF*m;
        w[d] = val; mx = fmaxf(mx, val);
    }
    float s = 0.f;
#pragma unroll
    for (int d = 0; d < 16; d++) { w[d] = expf(w[d]-mx); s += w[d]; }
    float inv = 1.f/s;
#pragma unroll
    for (int d = 0; d < 16; d++) g_dest[bv*16 + d] = w[d]*inv;
}

// ---------------- rev-gather + sparsemax ------------------------------------
extern "C" __global__ void k_sparse(const int* __restrict__ adj,
                                    const int* __restrict__ num_nodes) {
    int bv = blockIdx.x*128 + threadIdx.x;
    if (bv >= NB*NV) return;
    int b = bv / NV;
    int nn = num_nodes[b];
    float z[16], valid[16];
#pragma unroll
    for (int d = 0; d < 16; d++) {
        int a = adj[bv*16 + d];
        float m = (a == nn) ? 1.f : 0.f;
        valid[d] = 1.f - m;
        z[d] = g_dest[(b*NV + min(a, NV-1))*ND + d] - BIGF*m;
    }
    float zs[16];
    for (int d = 0; d < 16; d++) zs[d] = z[d];
    for (int i = 1; i < 16; i++) {            // insertion sort descending
        float key = zs[i]; int j = i-1;
        while (j >= 0 && zs[j] < key) { zs[j+1] = zs[j]; j--; }
        zs[j+1] = key;
    }
    float csum = 0.f, zck = 0.f; int kz = 1;
    for (int k = 1; k <= 16; k++) {
        csum += zs[k-1];
        if (1.f + (float)k*zs[k-1] > csum) { kz = k; zck = csum; }
    }
    float tau = (zck - 1.f)/(float)kz;
#pragma unroll
    for (int d = 0; d < 16; d++)
        g_norm[bv*16 + d] = fmaxf(z[d] - tau, 0.f) * valid[d];
}

// ---------------- min-cost-flow iterations (per-batch block) ----------------
extern "C" __global__ void __launch_bounds__(1024,1)
k_flow(const float* __restrict__ demands, const int* __restrict__ inv_adj) {
    extern __shared__ float sm[];
    float* flow_s = sm;          // V*D
    float* red    = sm + VD;     // 1024
    int b = blockIdx.x, v = threadIdx.x;
    int base = (b*NV + v)*ND;
    float nrm[16]; int ia[16];
#pragma unroll
    for (int d = 0; d < 16; d++) {
        nrm[d] = g_norm[base + d];
        ia[d]  = min(inv_adj[base + d], NV-1);
        flow_s[v*16 + d] = 0.f;
    }
    float dem = demands[b*NV + v];
    __syncthreads();
    for (int it = 0; it < 10; it++) {
        float inflow = 0.f;
#pragma unroll
        for (int d = 0; d < 16; d++) inflow += flow_s[ia[d]*16 + d];
        float val = fmaxf(inflow - dem, 0.f);
        __syncthreads();
#pragma unroll
        for (int d = 0; d < 16; d++) flow_s[v*16 + d] = nrm[d]*val;
        __syncthreads();
    }
    float c = 0.f;
#pragma unroll
    for (int d = 0; d < 16; d++) { float f = flow_s[v*16 + d]; c += f*f; }
    red[v] = c; __syncthreads();
    for (int s = 512; s > 0; s >>= 1) { if (v < s) red[v] += red[v+s]; __syncthreads(); }
    if (v == 0) g_flowcost[b] = red[0];
}

// ---------------- dual vars MLP (per node) ----------------------------------
extern "C" __global__ void k_dualvars(const float* __restrict__ W1,
                                      const float* __restrict__ b1,
                                      const float* __restrict__ W2,
                                      const float* __restrict__ b2) {
    int bv = blockIdx.x, t = threadIdx.x;  // 128 threads
    __shared__ float ns[128];
    __shared__ float hid[64];
    float s = 0.f;
#pragma unroll
    for (int d = 0; d < 16; d++) s += g_h[((size_t)bv*ND + d)*NH + t];
    ns[t] = s;
    __syncthreads();
    if (t < 64) {
        float a = b1[t];
        for (int k = 0; k < 128; k++) a += ns[k]*W1[k*NHD + t];
        hid[t] = tanhf(a) * W2[t];
    }
    __syncthreads();
    for (int st = 32; st > 0; st >>= 1) { if (t < st) hid[t] += hid[t+st]; __syncthreads(); }
    if (t == 0) g_dualvars[bv] = fmaxf(hid[0] + b2[0], 0.f);
}

// ---------------- dual flows + final output ---------------------------------
extern "C" __global__ void k_final(const float* __restrict__ demands,
                                   const int* __restrict__ adj,
                                   const int* __restrict__ num_nodes,
                                   float* __restrict__ out) {
    int b = blockIdx.x, tid = threadIdx.x;  // 256 threads
    int nn = num_nodes[b];
    __shared__ float red[256];
    float ddem = 0.f;
    for (int v = tid; v < NV; v += 256)
        ddem += g_dualvars[b*NV + v]*demands[b*NV + v];
    float ec = 0.f;
    for (int i = tid; i < VD; i += 256) {
        int v = i >> 4;
        int a = adj[b*VD + i];
        float m = (a == nn) ? 1.f : 0.f;
        float valid = 1.f - m;
        float dvv = g_dualvars[b*NV + v];
        float dual = m*dvv;
        float dtr = g_dualvars[b*NV + min(a, NV-1)]*valid;
        float dd = dtr - dual;
        float f = 0.f, vel = 0.f;
#pragma unroll
        for (int it = 0; it < 10; it++) {
            float grad = 2.f*f + dd;
            vel = 0.9f*vel - 0.01f*grad;
            f = fmaxf(f + vel, 0.f);
        }
        float df = f*valid;
        ec += df*df + dd*df;
    }
    red[tid] = ec - ddem;
    __syncthreads();
    for (int s = 128; s > 0; s >>= 1) { if (tid < s) red[tid] += red[tid+s]; __syncthreads(); }
    if (tid == 0) out[b] = g_flowcost[b] - red[0];  // flow_cost - dual_cost
}

// ---------------- launch ------------------------------------------------------
#define GAT_SMEM  ((16384+8192+1024+128+64+64)*4)
#define GRU_SMEM  ((8192+8192+16384+16384)*4)
#define DEC_SMEM  ((16384+16384+1024+64)*4)
#define FLOW_SMEM ((VD+1024)*4)

extern "C" void kernel_launch(void* const* d_in, const int* in_sizes, int n_in,
                              void* d_out, int out_size) {
    const float* demands       = (const float*)d_in[0];
    const float* node_features = (const float*)d_in[1];
    const float* node_emb      = (const float*)d_in[4];
    const float* W_enc   = (const float*)d_in[5];
    const float* b_enc   = (const float*)d_in[6];
    const float* W_gat   = (const float*)d_in[7];
    const float* b_gat   = (const float*)d_in[8];
    const float* a_gat   = (const float*)d_in[9];
    const float* W_gru_x = (const float*)d_in[10];
    const float* W_gru_h = (const float*)d_in[11];
    const float* b_gru   = (const float*)d_in[12];
    const float* W_dec1  = (const float*)d_in[13];
    const float* b_dec1  = (const float*)d_in[14];
    const float* W_dec2  = (const float*)d_in[15];
    const float* b_dec2  = (const float*)d_in[16];
    const float* W_dual1 = (const float*)d_in[17];
    const float* b_dual1 = (const float*)d_in[18];
    const float* W_dual2 = (const float*)d_in[19];
    const float* b_dual2 = (const float*)d_in[20];
    const int* adj       = (const int*)d_in[21];
    const int* inv_adj   = (const int*)d_in[22];
    const int* num_nodes = (const int*)d_in[26];
    float* out = (float*)d_out;

    cudaFuncSetAttribute(k_gat,  cudaFuncAttributeMaxDynamicSharedMemorySize, GAT_SMEM);
    cudaFuncSetAttribute(k_gru,  cudaFuncAttributeMaxDynamicSharedMemorySize, GRU_SMEM);
    cudaFuncSetAttribute(k_dec,  cudaFuncAttributeMaxDynamicSharedMemorySize, DEC_SMEM);
    cudaFuncSetAttribute(k_flow, cudaFuncAttributeMaxDynamicSharedMemorySize, FLOW_SMEM);

    k_enc0<<<NV, 128>>>(node_emb, W_enc);
    k_nodeenc<<<NB*NV, 128>>>(node_features, W_enc, b_enc);
    k_inith<<<ROWS_TOTAL, 128>>>(adj, num_nodes);
    for (int L = 0; L < 2; L++) {
        k_gat<<<ROWS_TOTAL/64, 256, GAT_SMEM>>>(W_gat, b_gat, a_gat, adj, num_nodes);
        k_gru<<<ROWS_TOTAL/64, 256, GRU_SMEM>>>(W_gru_x, W_gru_h, b_gru, adj, num_nodes);
    }
    k_dec<<<ROWS_TOTAL/64, 256, DEC_SMEM>>>(W_dec1, b_dec1, W_dec2, b_dec2, adj);
    k_dest<<<(NB*NV)/128, 128>>>(inv_adj, num_nodes);
    k_sparse<<<(NB*NV)/128, 128>>>(adj, num_nodes);
    k_flow<<<NB, 1024, FLOW_SMEM>>>(demands, inv_adj);
    k_dualvars<<<NB*NV, 128>>>(W_dual1, b_dual1, W_dual2, b_dual2);
    k_final<<<NB, 256>>>(demands, adj, num_nodes, out);
}

// round 2
// speedup vs baseline: 2.6756x; 2.6756x over previous
#include <cuda_runtime.h>
#include <math.h>

#define NB 16
#define NV 1024
#define ND 16
#define NE 64
#define NF 16
#define NH 128
#define NHD 64
#define BIGF 1e9f
#define VD (NV*ND)
#define ROWS_TOTAL (NB*VD)
#define NNODES (NB*NV)

__device__ float g_h[(size_t)ROWS_TOTAL*NH];
__device__ float g_uw[(size_t)ROWS_TOTAL*NH];
__device__ float g_nodeenc[NNODES*NH];
__device__ float g_tnode[NNODES*NH];
__device__ float g_xnode[NNODES*NH];
__device__ float g_lnode[NNODES];
__device__ float g_gx[NNODES*3*NH];
__device__ float g_gh1[NNODES*3*NH];
__device__ float g_enc0[NV*NH];
__device__ float g_nw[ROWS_TOTAL];
__device__ float g_dest[ROWS_TOTAL];
__device__ float g_norm[ROWS_TOTAL];
__device__ float g_dualvars[NNODES];
__device__ float g_flowcost[NB];
__device__ float g_wcomb[NH*NH];

__device__ __forceinline__ float sigmoidf_(float x) { return 1.f/(1.f+expf(-x)); }

__device__ __forceinline__ void mm_acc128(const float* __restrict__ As,
                                          const float* __restrict__ Ws,
                                          int r4, int c8, float (&acc)[4][8]) {
#pragma unroll 2
    for (int k4 = 0; k4 < 128; k4 += 4) {
        float a[4][4];
#pragma unroll
        for (int i = 0; i < 4; i++) {
            float4 v = *(const float4*)(As + (r4+i)*128 + k4);
            a[i][0]=v.x; a[i][1]=v.y; a[i][2]=v.z; a[i][3]=v.w;
        }
#pragma unroll
        for (int kk = 0; kk < 4; kk++) {
            float4 w0 = *(const float4*)(Ws + (k4+kk)*128 + c8);
            float4 w1 = *(const float4*)(Ws + (k4+kk)*128 + c8 + 4);
            float w[8] = {w0.x,w0.y,w0.z,w0.w,w1.x,w1.y,w1.z,w1.w};
#pragma unroll
            for (int i = 0; i < 4; i++)
#pragma unroll
                for (int j = 0; j < 8; j++)
                    acc[i][j] += a[i][kk]*w[j];
        }
    }
}

extern "C" __global__ void k_enc0(const float* __restrict__ emb,
                                  const float* __restrict__ W_enc) {
    int v = blockIdx.x, t = threadIdx.x;
    __shared__ float e_s[NE];
    __shared__ float red[128];
    if (t < NE) e_s[t] = emb[v*NE + t];
    __syncthreads();
    float sq = (t < NE) ? e_s[t]*e_s[t] : 0.f;
    red[t] = sq; __syncthreads();
    for (int s = 64; s > 0; s >>= 1) { if (t < s) red[t] += red[t+s]; __syncthreads(); }
    float inv = 1.f / fmaxf(sqrtf(red[0]), 1.f);
    float acc = 0.f;
    for (int k = 0; k < NE; k++) acc += e_s[k]*inv*W_enc[k*NH + t];
    g_enc0[v*NH + t] = acc;
}

extern "C" __global__ void k_nodeenc(const float* __restrict__ nf,
                                     const float* __restrict__ W_enc,
                                     const float* __restrict__ b_enc) {
    int bv = blockIdx.x, t = threadIdx.x;
    int v = bv % NV;
    __shared__ float f_s[NF];
    if (t < NF) f_s[t] = nf[bv*NF + t];
    __syncthreads();
    float acc = g_enc0[v*NH + t] + b_enc[t];
    for (int k = 0; k < NF; k++) acc += f_s[k]*W_enc[(NE+k)*NH + t];
    g_nodeenc[bv*NH + t] = acc;
}

extern "C" __global__ void __launch_bounds__(256,2)
k_tnode(const float* __restrict__ W_gat, const float* __restrict__ b_gat,
        const float* __restrict__ a_gat) {
    extern __shared__ float sm[];
    float* W_s = sm;
    float* A_s = sm + 16384;
    float* red = sm + 24576;
    const int tid = threadIdx.x;
    const int r0 = blockIdx.x*64;
    for (int i = tid; i < 16384; i += 256) W_s[i] = W_gat[i];
    for (int i = tid; i < 8192;  i += 256) A_s[i] = g_nodeenc[(size_t)r0*128 + i];
    __syncthreads();
    const int c8 = (tid & 15)*8, r4 = (tid >> 4)*4;
    float acc[4][8];
#pragma unroll
    for (int i = 0; i < 4; i++)
#pragma unroll
        for (int j = 0; j < 8; j++) acc[i][j] = b_gat[c8+j];
    mm_acc128(A_s, W_s, r4, c8, acc);
#pragma unroll
    for (int i = 0; i < 4; i++) {
        float p = 0.f;
#pragma unroll
        for (int j = 0; j < 8; j++) {
            acc[i][j] = tanhf(acc[i][j]);
            p += acc[i][j]*a_gat[c8+j];
        }
        size_t base = (size_t)(r0+r4+i)*128 + c8;
        *(float4*)(g_tnode + base)   = make_float4(acc[i][0],acc[i][1],acc[i][2],acc[i][3]);
        *(float4*)(g_tnode + base+4) = make_float4(acc[i][4],acc[i][5],acc[i][6],acc[i][7]);
        red[(r4+i)*16 + (tid & 15)] = p;
    }
    __syncthreads();
    if (tid < 64) {
        float s = 0.f;
#pragma unroll
        for (int c = 0; c < 16; c++) s += red[tid*16 + c];
        g_lnode[r0 + tid] = s;
    }
}

// mode: 0 -> A=g_xnode, out=g_gx ; 1 -> A=g_nodeenc, out=g_gh1
extern "C" __global__ void __launch_bounds__(256,2)
k_ngemm384(const float* __restrict__ W, int mode) {
    extern __shared__ float sm[];
    float* W_s = sm;
    float* A_s = sm + 16384;
    const float* A = (mode == 0) ? g_xnode : g_nodeenc;
    float* out     = (mode == 0) ? g_gx    : g_gh1;
    const int tid = threadIdx.x;
    const int r0 = blockIdx.x*64;
    const int g  = blockIdx.y;
    for (int i = tid; i < 16384; i += 256) {
        int k = i >> 7, c = i & 127;
        W_s[i] = W[k*384 + g*128 + c];
    }
    for (int i = tid; i < 8192; i += 256) A_s[i] = A[(size_t)r0*128 + i];
    __syncthreads();
    const int c8 = (tid & 15)*8, r4 = (tid >> 4)*4;
    float acc[4][8];
#pragma unroll
    for (int i = 0; i < 4; i++)
#pragma unroll
        for (int j = 0; j < 8; j++) acc[i][j] = 0.f;
    mm_acc128(A_s, W_s, r4, c8, acc);
#pragma unroll
    for (int i = 0; i < 4; i++) {
        size_t base = (size_t)(r0+r4+i)*384 + g*128 + c8;
        *(float4*)(out + base)   = make_float4(acc[i][0],acc[i][1],acc[i][2],acc[i][3]);
        *(float4*)(out + base+4) = make_float4(acc[i][4],acc[i][5],acc[i][6],acc[i][7]);
    }
}

extern "C" __global__ void k_attn1(const int* __restrict__ adj,
                                   const int* __restrict__ num_nodes,
                                   const float* __restrict__ b_gat,
                                   const float* __restrict__ a_gat) {
    int n = blockIdx.x;
    int t = threadIdx.x;
    int b = n >> 10;
    __shared__ float red[128];
    __shared__ float at[16];
    __shared__ int   adjs[16];
    __shared__ float vals[16];
    float tb = tanhf(b_gat[t]);
    red[t] = tb * a_gat[t];
    if (t < 16) {
        int a = adj[n*16 + t];
        vals[t] = (a == num_nodes[b]) ? 0.f : 1.f;
        adjs[t] = b*NV + min(a, NV-1);
    }
    __syncthreads();
    for (int s = 64; s > 0; s >>= 1) { if (t < s) red[t] += red[t+s]; __syncthreads(); }
    if (t == 0) {
        float tbdot = red[0] - BIGF;
        float lg[16]; float mx = -1e30f;
#pragma unroll
        for (int d = 0; d < 16; d++) {
            lg[d] = (vals[d] != 0.f) ? g_lnode[adjs[d]] : tbdot;
            mx = fmaxf(mx, lg[d]);
        }
        float ssum = 0.f;
#pragma unroll
        for (int d = 0; d < 16; d++) { lg[d] = expf(lg[d]-mx); ssum += lg[d]; }
        float inv = 1.f/ssum;
#pragma unroll
        for (int d = 0; d < 16; d++) at[d] = lg[d]*inv;
    }
    __syncthreads();
    float msg = 0.f;
#pragma unroll
    for (int d = 0; d < 16; d++) {
        float tv = (vals[d] != 0.f) ? g_tnode[(size_t)adjs[d]*128 + t] : tb;
        msg += at[d]*tv;
    }
    g_xnode[(size_t)n*128 + t] = tanhf(msg + g_nodeenc[(size_t)n*128 + t]);
}

extern "C" __global__ void k_comb1(const int* __restrict__ adj,
                                   const int* __restrict__ num_nodes,
                                   const float* __restrict__ bg) {
    int e   = blockIdx.x*2 + (threadIdx.x >> 7);
    int col = threadIdx.x & 127;
    int b = e / VD;
    int a = adj[e];
    float v = (a == num_nodes[b]) ? 0.f : 1.f;
    size_t an = (size_t)(b*NV + min(a, NV-1));
    float gxz = g_gx[an*384 + col];
    float gxr = g_gx[an*384 + 128 + col];
    float gxc = g_gx[an*384 + 256 + col];
    float ghz = g_gh1[an*384 + col];
    float ghr = g_gh1[an*384 + 128 + col];
    float ghc = g_gh1[an*384 + 256 + col];
    float h0  = g_nodeenc[an*128 + col];
    float z = sigmoidf_(v*(gxz + ghz) + bg[col]);
    float r = sigmoidf_(v*(gxr + ghr) + bg[128 + col]);
    float cand = tanhf(v*gxc + bg[256 + col] + r*(v*ghc));
    g_h[(size_t)e*128 + col] = z*(v*h0) + (1.f - z)*cand;
}

extern "C" __global__ void __launch_bounds__(256,2)
k_gat2(const float* __restrict__ W_gat, const float* __restrict__ b_gat,
       const float* __restrict__ a_gat, const int* __restrict__ adj,
       const int* __restrict__ num_nodes) {
    extern __shared__ float sm[];
    float* W_s = sm;
    float* h_s = W_s + 16384;
    float* red = h_s + 8192;
    float* a_s = red + 1024;
    float* lg  = a_s + 128;
    float* at  = lg + 64;
    const int tid = threadIdx.x;
    const int r0  = blockIdx.x * 64;
    const int b   = r0 / VD;
    const int nn  = num_nodes[b];

    for (int i = tid; i < 16384; i += 256) W_s[i] = W_gat[i];
    for (int i = tid; i < 8192;  i += 256) h_s[i] = g_h[(size_t)r0*NH + i];
    if (tid < 128) a_s[tid] = a_gat[tid];
    __syncthreads();

    const int c8 = (tid & 15)*8, r4 = (tid >> 4)*4;
    float acc[4][8];
#pragma unroll
    for (int i = 0; i < 4; i++)
#pragma unroll
        for (int j = 0; j < 8; j++) acc[i][j] = b_gat[c8+j];
    mm_acc128(h_s, W_s, r4, c8, acc);
#pragma unroll
    for (int i = 0; i < 4; i++)
#pragma unroll
        for (int j = 0; j < 8; j++) acc[i][j] = tanhf(acc[i][j]);
    __syncthreads();
#pragma unroll
    for (int i = 0; i < 4; i++) {
        int row = r4 + i; float p = 0.f;
#pragma unroll
        for (int j = 0; j < 8; j++) {
            float tv = acc[i][j];
            h_s[row*128 + c8 + j] = tv;
            p += tv * a_s[c8+j];
        }
        red[row*16 + (tid & 15)] = p;
    }
    __syncthreads();
    if (tid < 64) {
        float s = 0.f;
#pragma unroll
        for (int c = 0; c < 16; c++) s += red[tid*16 + c];
        int a = adj[r0 + tid];
        lg[tid] = s - ((a == nn) ? BIGF : 0.f);
    }
    __syncthreads();
    if (tid < 4) {
        float mx = -1e30f;
#pragma unroll
        for (int d = 0; d < 16; d++) mx = fmaxf(mx, lg[tid*16+d]);
        float e[16], ssum = 0.f;
#pragma unroll
        for (int d = 0; d < 16; d++) { e[d] = expf(lg[tid*16+d]-mx); ssum += e[d]; }
#pragma unroll
        for (int d = 0; d < 16; d++) at[tid*16+d] = e[d]/ssum;
    }
    __syncthreads();
    for (int i = tid; i < 512; i += 256) {
        int node = i >> 7, col = i & 127;
        float s = 0.f;
#pragma unroll
        for (int d = 0; d < 16; d++) s += at[node*16+d] * h_s[(node*16+d)*128 + col];
        size_t gn = (size_t)((r0 >> 4) + node);
        g_xnode[gn*NH + col] = tanhf(s + g_nodeenc[gn*NH + col]);
    }
}

extern "C" __global__ void __launch_bounds__(256,2)
k_gru2(const float* __restrict__ Wh, const float* __restrict__ bg,
       const int* __restrict__ adj, const int* __restrict__ num_nodes) {
    extern __shared__ float sm[];
    float* W_s = sm;
    float* h_s = sm + 16384;
    __shared__ int   adjs[64];
    __shared__ float vals[64];
    const int tid = threadIdx.x;
    const int r0  = blockIdx.x * 64;
    const int b   = r0 / VD;
    if (tid < 64) {
        int a = adj[r0 + tid];
        vals[tid] = (a == num_nodes[b]) ? 0.f : 1.f;
        adjs[tid] = b*NV + min(a, NV-1);
    }
    for (int i = tid; i < 8192; i += 256) h_s[i] = g_h[(size_t)r0*NH + i];
    const int c8 = (tid & 15)*8, r4 = (tid >> 4)*4;
    float zg[4][8], rg[4][8];
    for (int g = 0; g < 3; g++) {
        __syncthreads();
        for (int i = tid; i < 16384; i += 256) {
            int k = i >> 7, c = i & 127;
            W_s[i] = Wh[k*384 + g*128 + c];
        }
        __syncthreads();
        float acc[4][8];
#pragma unroll
        for (int i = 0; i < 4; i++)
#pragma unroll
            for (int j = 0; j < 8; j++) acc[i][j] = 0.f;
        mm_acc128(h_s, W_s, r4, c8, acc);
#pragma unroll
        for (int i = 0; i < 4; i++) {
            int row = r4 + i;
            float v = vals[row];
            size_t an = (size_t)adjs[row];
            float4 x0 = *(const float4*)(g_gx + an*384 + g*128 + c8);
            float4 x1 = *(const float4*)(g_gx + an*384 + g*128 + c8 + 4);
            float gx[8] = {x0.x,x0.y,x0.z,x0.w,x1.x,x1.y,x1.z,x1.w};
            if (g == 0) {
#pragma unroll
                for (int j = 0; j < 8; j++)
                    zg[i][j] = sigmoidf_(v*gx[j] + acc[i][j] + bg[c8+j]);
            } else if (g == 1) {
#pragma unroll
                for (int j = 0; j < 8; j++)
                    rg[i][j] = sigmoidf_(v*gx[j] + acc[i][j] + bg[128+c8+j]);
            } else {
                float outv[8];
#pragma unroll
                for (int j = 0; j < 8; j++) {
                    float cand = tanhf(v*gx[j] + bg[256+c8+j] + rg[i][j]*acc[i][j]);
                    float hold = h_s[row*128 + c8 + j];
                    outv[j] = zg[i][j]*hold + (1.f - zg[i][j])*cand;
                }
                size_t base = (size_t)(r0 + row)*NH + c8;
                *(float4*)(g_h + base)     = make_float4(outv[0],outv[1],outv[2],outv[3]);
                *(float4*)(g_h + base + 4) = make_float4(outv[4],outv[5],outv[6],outv[7]);
            }
        }
    }
}

extern "C" __global__ void k_wprep(const float* __restrict__ W1) {
    int t = blockIdx.x*256 + threadIdx.x;
    int k = t >> 7, c = t & 127;
    float v;
    if (c < 64) v = W1[k*64 + c] + W1[(128+k)*64 + c];
    else        v = W1[(128+k)*64 + (c-64)];
    g_wcomb[t] = v;
}

extern "C" __global__ void __launch_bounds__(256,2)
k_dec1() {
    extern __shared__ float sm[];
    float* W_s = sm;
    float* h_s = sm + 16384;
    const int tid = threadIdx.x;
    const int r0 = blockIdx.x*64;
    for (int i = tid; i < 16384; i += 256) W_s[i] = g_wcomb[i];
    for (int i = tid; i < 8192;  i += 256) h_s[i] = g_h[(size_t)r0*NH + i];
    __syncthreads();
    const int c8 = (tid & 15)*8, r4 = (tid >> 4)*4;
    float acc[4][8];
#pragma unroll
    for (int i = 0; i < 4; i++)
#pragma unroll
        for (int j = 0; j < 8; j++) acc[i][j] = 0.f;
    mm_acc128(h_s, W_s, r4, c8, acc);
#pragma unroll
    for (int i = 0; i < 4; i++) {
        size_t base = (size_t)(r0+r4+i)*NH + c8;
        *(float4*)(g_uw + base)   = make_float4(acc[i][0],acc[i][1],acc[i][2],acc[i][3]);
        *(float4*)(g_uw + base+4) = make_float4(acc[i][4],acc[i][5],acc[i][6],acc[i][7]);
    }
}

extern "C" __global__ void k_dec2(const float* __restrict__ b1,
                                  const float* __restrict__ W2,
                                  const float* __restrict__ b2,
                                  const int* __restrict__ adj) {
    int e = blockIdx.x*8 + (threadIdx.x >> 5);
    int lane = threadIdx.x & 31;
    int b = e / VD;
    int d = e & 15;
    int a = min(adj[e], NV-1);
    size_t opp = ((size_t)(b*NV + a))*ND + (d ^ 1);
    float s = 0.f;
#pragma unroll
    for (int j = lane; j < 64; j += 32) {
        float pre = g_uw[(size_t)e*NH + j] + g_uw[opp*NH + 64 + j] + b1[j];
        s += tanhf(pre)*W2[j];
    }
#pragma unroll
    for (int o = 16; o > 0; o >>= 1) s += __shfl_down_sync(0xffffffff, s, o);
    if (lane == 0) g_nw[e] = s + b2[0];
}

extern "C" __global__ void k_dest(const int* __restrict__ inv_adj,
                                  const int* __restrict__ num_nodes) {
    int bv = blockIdx.x*128 + threadIdx.x;
    if (bv >= NNODES) return;
    int b = bv >> 10;
    int nn = num_nodes[b];
    float w[16]; float mx = -1e30f;
#pragma unroll
    for (int d = 0; d < 16; d++) {
        int ia = inv_adj[bv*16 + d];
        float m = (ia == nn) ? 1.f : 0.f;
        float val = g_nw[(b*NV + min(ia, NV-1))*ND + d] - BIGF*m;
        w[d] = val; mx = fmaxf(mx, val);
    }
    float s = 0.f;
#pragma unroll
    for (int d = 0; d < 16; d++) { w[d] = expf(w[d]-mx); s += w[d]; }
    float inv = 1.f/s;
#pragma unroll
    for (int d = 0; d < 16; d++) g_dest[bv*16 + d] = w[d]*inv;
}

extern "C" __global__ void k_sparse(const int* __restrict__ adj,
                                    const int* __restrict__ num_nodes) {
    int bv = blockIdx.x*128 + threadIdx.x;
    if (bv >= NNODES) return;
    int b = bv >> 10;
    int nn = num_nodes[b];
    float z[16], valid[16];
#pragma unroll
    for (int d = 0; d < 16; d++) {
        int a = adj[bv*16 + d];
        float m = (a == nn) ? 1.f : 0.f;
        valid[d] = 1.f - m;
        z[d] = g_dest[(b*NV + min(a, NV-1))*ND + d] - BIGF*m;
    }
    float zs[16];
    for (int d = 0; d < 16; d++) zs[d] = z[d];
    for (int i = 1; i < 16; i++) {
        float key = zs[i]; int j = i-1;
        while (j >= 0 && zs[j] < key) { zs[j+1] = zs[j]; j--; }
        zs[j+1] = key;
    }
    float csum = 0.f, zck = 0.f; int kz = 1;
    for (int k = 1; k <= 16; k++) {
        csum += zs[k-1];
        if (1.f + (float)k*zs[k-1] > csum) { kz = k; zck = csum; }
    }
    float tau = (zck - 1.f)/(float)kz;
#pragma unroll
    for (int d = 0; d < 16; d++)
        g_norm[bv*16 + d] = fmaxf(z[d] - tau, 0.f) * valid[d];
}

extern "C" __global__ void __launch_bounds__(1024,1)
k_flow(const float* __restrict__ demands, const int* __restrict__ inv_adj) {
    extern __shared__ float sm[];
    float* flow_s = sm;
    float* red    = sm + VD;
    int b = blockIdx.x, v = threadIdx.x;
    int base = (b*NV + v)*ND;
    float nrm[16]; int ia[16];
#pragma unroll
    for (int d = 0; d < 16; d++) {
        nrm[d] = g_norm[base + d];
        ia[d]  = min(inv_adj[base + d], NV-1);
        flow_s[v*16 + d] = 0.f;
    }
    float dem = demands[b*NV + v];
    __syncthreads();
    for (int it = 0; it < 10; it++) {
        float inflow = 0.f;
#pragma unroll
        for (int d = 0; d < 16; d++) inflow += flow_s[ia[d]*16 + d];
        float val = fmaxf(inflow - dem, 0.f);
        __syncthreads();
#pragma unroll
        for (int d = 0; d < 16; d++) flow_s[v*16 + d] = nrm[d]*val;
        __syncthreads();
    }
    float c = 0.f;
#pragma unroll
    for (int d = 0; d < 16; d++) { float f = flow_s[v*16 + d]; c += f*f; }
    red[v] = c; __syncthreads();
    for (int s = 512; s > 0; s >>= 1) { if (v < s) red[v] += red[v+s]; __syncthreads(); }
    if (v == 0) g_flowcost[b] = red[0];
}

extern "C" __global__ void k_dualvars(const float* __restrict__ W1,
                                      const float* __restrict__ b1,
                                      const float* __restrict__ W2,
                                      const float* __restrict__ b2) {
    int bv = blockIdx.x, t = threadIdx.x;
    __shared__ float ns[128];
    __shared__ float hid[64];
    float s = 0.f;
#pragma unroll
    for (int d = 0; d < 16; d++) s += g_h[((size_t)bv*ND + d)*NH + t];
    ns[t] = s;
    __syncthreads();
    if (t < 64) {
        float a = b1[t];
        for (int k = 0; k < 128; k++) a += ns[k]*W1[k*NHD + t];
        hid[t] = tanhf(a) * W2[t];
    }
    __syncthreads();
    for (int st = 32; st > 0; st >>= 1) { if (t < st) hid[t] += hid[t+st]; __syncthreads(); }
    if (t == 0) g_dualvars[bv] = fmaxf(hid[0] + b2[0], 0.f);
}

extern "C" __global__ void k_final(const float* __restrict__ demands,
                                   const int* __restrict__ adj,
                                   const int* __restrict__ num_nodes,
                                   float* __restrict__ out) {
    int b = blockIdx.x, tid = threadIdx.x;
    int nn = num_nodes[b];
    __shared__ float red[256];
    float ddem = 0.f;
    for (int v = tid; v < NV; v += 256)
        ddem += g_dualvars[b*NV + v]*demands[b*NV + v];
    float ec = 0.f;
    for (int i = tid; i < VD; i += 256) {
        int v = i >> 4;
        int a = adj[b*VD + i];
        float m = (a == nn) ? 1.f : 0.f;
        float valid = 1.f - m;
        float dvv = g_dualvars[b*NV + v];
        float dual = m*dvv;
        float dtr = g_dualvars[b*NV + min(a, NV-1)]*valid;
        float dd = dtr - dual;
        float f = 0.f, vel = 0.f;
#pragma unroll
        for (int it = 0; it < 10; it++) {
            float grad = 2.f*f + dd;
            vel = 0.9f*vel - 0.01f*grad;
            f = fmaxf(f + vel, 0.f);
        }
        float df = f*valid;
        ec += df*df + dd*df;
    }
    red[tid] = ec - ddem;
    __syncthreads();
    for (int s = 128; s > 0; s >>= 1) { if (tid < s) red[tid] += red[tid+s]; __syncthreads(); }
    if (tid == 0) out[b] = g_flowcost[b] - red[0];
}

#define TNODE_SMEM ((16384+8192+1024)*4)
#define NGEMM_SMEM ((16384+8192)*4)
#define GAT2_SMEM  ((16384+8192+1024+128+64+64)*4)
#define GRU2_SMEM  ((16384+8192)*4)
#define DEC1_SMEM  ((16384+8192)*4)
#define FLOW_SMEM  ((VD+1024)*4)

extern "C" void kernel_launch(void* const* d_in, const int* in_sizes, int n_in,
                              void* d_out, int out_size) {
    const float* demands       = (const float*)d_in[0];
    const float* node_features = (const float*)d_in[1];
    const float* node_emb      = (const float*)d_in[4];
    const float* W_enc   = (const float*)d_in[5];
    const float* b_enc   = (const float*)d_in[6];
    const float* W_gat   = (const float*)d_in[7];
    const float* b_gat   = (const float*)d_in[8];
    const float* a_gat   = (const float*)d_in[9];
    const float* W_gru_x = (const float*)d_in[10];
    const float* W_gru_h = (const float*)d_in[11];
    const float* b_gru   = (const float*)d_in[12];
    const float* W_dec1  = (const float*)d_in[13];
    const float* b_dec1  = (const float*)d_in[14];
    const float* W_dec2  = (const float*)d_in[15];
    const float* b_dec2  = (const float*)d_in[16];
    const float* W_dual1 = (const float*)d_in[17];
    const float* b_dual1 = (const float*)d_in[18];
    const float* W_dual2 = (const float*)d_in[19];
    const float* b_dual2 = (const float*)d_in[20];
    const int* adj       = (const int*)d_in[21];
    const int* inv_adj   = (const int*)d_in[22];
    const int* num_nodes = (const int*)d_in[26];
    float* out = (float*)d_out;

    cudaFuncSetAttribute(k_tnode,    cudaFuncAttributeMaxDynamicSharedMemorySize, TNODE_SMEM);
    cudaFuncSetAttribute(k_ngemm384, cudaFuncAttributeMaxDynamicSharedMemorySize, NGEMM_SMEM);
    cudaFuncSetAttribute(k_gat2,     cudaFuncAttributeMaxDynamicSharedMemorySize, GAT2_SMEM);
    cudaFuncSetAttribute(k_gru2,     cudaFuncAttributeMaxDynamicSharedMemorySize, GRU2_SMEM);
    cudaFuncSetAttribute(k_dec1,     cudaFuncAttributeMaxDynamicSharedMemorySize, DEC1_SMEM);
    cudaFuncSetAttribute(k_flow,     cudaFuncAttributeMaxDynamicSharedMemorySize, FLOW_SMEM);

    dim3 ng(NNODES/64, 3);

    k_enc0<<<NV, 128>>>(node_emb, W_enc);
    k_nodeenc<<<NNODES, 128>>>(node_features, W_enc, b_enc);
    k_wprep<<<64, 256>>>(W_dec1);

    // ---- layer 1: node-level only ----
    k_tnode<<<NNODES/64, 256, TNODE_SMEM>>>(W_gat, b_gat, a_gat);
    k_attn1<<<NNODES, 128>>>(adj, num_nodes, b_gat, a_gat);
    k_ngemm384<<<ng, 256, NGEMM_SMEM>>>(W_gru_h, 1);   // g_gh1 = node_enc @ Wh
    k_ngemm384<<<ng, 256, NGEMM_SMEM>>>(W_gru_x, 0);   // g_gx  = xnode @ Wx
    k_comb1<<<ROWS_TOTAL/2, 256>>>(adj, num_nodes, b_gru);

    // ---- layer 2 ----
    k_gat2<<<ROWS_TOTAL/64, 256, GAT2_SMEM>>>(W_gat, b_gat, a_gat, adj, num_nodes);
    k_ngemm384<<<ng, 256, NGEMM_SMEM>>>(W_gru_x, 0);   // g_gx = xnode2 @ Wx
    k_gru2<<<ROWS_TOTAL/64, 256, GRU2_SMEM>>>(W_gru_h, b_gru, adj, num_nodes);

    // ---- decoder ----
    k_dec1<<<ROWS_TOTAL/64, 256, DEC1_SMEM>>>();
    k_dec2<<<ROWS_TOTAL/8, 256>>>(b_dec1, W_dec2, b_dec2, adj);

    // ---- flow / dual / output ----
    k_dest<<<NNODES/128, 128>>>(inv_adj, num_nodes);
    k_sparse<<<NNODES/128, 128>>>(adj, num_nodes);
    k_flow<<<NB, 1024, FLOW_SMEM>>>(demands, inv_adj);
    k_dualvars<<<NNODES, 128>>>(W_dual1, b_dual1, W_dual2, b_dual2);
    k_final<<<NB, 256>>>(demands, adj, num_nodes, out);
}

// round 3
// speedup vs baseline: 9.5727x; 3.5778x over previous
#include <cuda_runtime.h>
#include <math.h>

#define NB 16
#define NV 1024
#define ND 16
#define NE 64
#define NF 16
#define NH 128
#define NHD 64
#define BIGF 1e9f
#define VD (NV*ND)
#define ROWS_TOTAL (NB*VD)
#define NNODES (NB*NV)

// ---- node-level scratch (everything small; L2-resident) --------------------
__device__ float g_nodeenc[NNODES*NH];
__device__ float g_xnode[NNODES*NH];
__device__ float g_tnode[NNODES*NH];
__device__ float g_lnode[NNODES];
__device__ float g_hn1[NNODES*NH];     // H1 (node-level layer-1 output)
__device__ float g_hn2[NNODES*NH];     // H2
__device__ float g_gx[NNODES*3*NH];
__device__ float g_gh[NNODES*3*NH];
__device__ float g_uwn[NNODES*NH];     // H2 @ wcomb
__device__ float g_enc0[NV*NH];
__device__ float g_wcomb[NH*NH];
// pads (masked-edge constants)
__device__ float g_tpad[NH];
__device__ float g_lpad[1];
__device__ float g_h2pad[NH];
__device__ float g_uwpad[NH];
// per-edge scalars
__device__ float g_nw[ROWS_TOTAL];
__device__ float g_dest[ROWS_TOTAL];
__device__ float g_norm[ROWS_TOTAL];
__device__ float g_dualvars[NNODES];
__device__ float g_flowcost[NB];

__device__ __forceinline__ float sigmoidf_(float x) { return 1.f/(1.f+expf(-x)); }

__device__ __forceinline__ void mm_acc128(const float* __restrict__ As,
                                          const float* __restrict__ Ws,
                                          int r4, int c8, float (&acc)[4][8]) {
#pragma unroll 2
    for (int k4 = 0; k4 < 128; k4 += 4) {
        float a[4][4];
#pragma unroll
        for (int i = 0; i < 4; i++) {
            float4 v = *(const float4*)(As + (r4+i)*128 + k4);
            a[i][0]=v.x; a[i][1]=v.y; a[i][2]=v.z; a[i][3]=v.w;
        }
#pragma unroll
        for (int kk = 0; kk < 4; kk++) {
            float4 w0 = *(const float4*)(Ws + (k4+kk)*128 + c8);
            float4 w1 = *(const float4*)(Ws + (k4+kk)*128 + c8 + 4);
            float w[8] = {w0.x,w0.y,w0.z,w0.w,w1.x,w1.y,w1.z,w1.w};
#pragma unroll
            for (int i = 0; i < 4; i++)
#pragma unroll
                for (int j = 0; j < 8; j++)
                    acc[i][j] += a[i][kk]*w[j];
        }
    }
}

// ---------------- encoding --------------------------------------------------
extern "C" __global__ void k_enc0(const float* __restrict__ emb,
                                  const float* __restrict__ W_enc) {
    int v = blockIdx.x, t = threadIdx.x;
    __shared__ float e_s[NE];
    __shared__ float red[128];
    if (t < NE) e_s[t] = emb[v*NE + t];
    __syncthreads();
    float sq = (t < NE) ? e_s[t]*e_s[t] : 0.f;
    red[t] = sq; __syncthreads();
    for (int s = 64; s > 0; s >>= 1) { if (t < s) red[t] += red[t+s]; __syncthreads(); }
    float inv = 1.f / fmaxf(sqrtf(red[0]), 1.f);
    float acc = 0.f;
    for (int k = 0; k < NE; k++) acc += e_s[k]*inv*W_enc[k*NH + t];
    g_enc0[v*NH + t] = acc;
}

extern "C" __global__ void k_nodeenc(const float* __restrict__ nf,
                                     const float* __restrict__ W_enc,
                                     const float* __restrict__ b_enc) {
    int bv = blockIdx.x, t = threadIdx.x;
    int v = bv % NV;
    __shared__ float f_s[NF];
    if (t < NF) f_s[t] = nf[bv*NF + t];
    __syncthreads();
    float acc = g_enc0[v*NH + t] + b_enc[t];
    for (int k = 0; k < NF; k++) acc += f_s[k]*W_enc[(NE+k)*NH + t];
    g_nodeenc[bv*NH + t] = acc;
}

// ---------------- decoder combined weight ------------------------------------
extern "C" __global__ void k_wprep(const float* __restrict__ W1) {
    int t = blockIdx.x*256 + threadIdx.x;
    int k = t >> 7, c = t & 127;
    float v;
    if (c < 64) v = W1[k*64 + c] + W1[(128+k)*64 + c];
    else        v = W1[(128+k)*64 + (c-64)];
    g_wcomb[t] = v;
}

// ---------------- masked-edge pad vectors (1 block, 128 threads) -------------
extern "C" __global__ void k_pads(const float* __restrict__ bg,
                                  const float* __restrict__ Wh,
                                  const float* __restrict__ W_gat,
                                  const float* __restrict__ b_gat,
                                  const float* __restrict__ a_gat) {
    int t = threadIdx.x;  // 128
    __shared__ float h1p[128], ghp[384], h2ps[128], red[128];
    // layer-1 masked fixed point: h1pad = (1-sig(b_z))*tanh(b_c)
    h1p[t] = (1.f - sigmoidf_(bg[t])) * tanhf(bg[256+t]);
    __syncthreads();
    // ghpad = h1pad @ Wh
    for (int g = 0; g < 3; g++) {
        float s = 0.f;
        for (int k = 0; k < 128; k++) s += h1p[k]*Wh[k*384 + g*128 + t];
        ghp[g*128 + t] = s;
    }
    // tpad2 = tanh(h1pad @ Wgat + b_gat); lpad2 = tpad2 . a_gat
    float s = b_gat[t];
    for (int k = 0; k < 128; k++) s += h1p[k]*W_gat[k*128 + t];
    float t2 = tanhf(s);
    g_tpad[t] = t2;
    red[t] = t2*a_gat[t];
    __syncthreads();
    for (int st = 64; st > 0; st >>= 1) { if (t < st) red[t] += red[t+st]; __syncthreads(); }
    if (t == 0) g_lpad[0] = red[0];
    // h2pad
    float z = sigmoidf_(bg[t] + ghp[t]);
    float r = sigmoidf_(bg[128+t] + ghp[128+t]);
    float cand = tanhf(bg[256+t] + r*ghp[256+t]);
    float h2p = z*h1p[t] + (1.f - z)*cand;
    g_h2pad[t] = h2p;
    h2ps[t] = h2p;
    __syncthreads();
    // uwpad = h2pad @ wcomb
    float u = 0.f;
    for (int k = 0; k < 128; k++) u += h2ps[k]*g_wcomb[k*128 + t];
    g_uwpad[t] = u;
}

// ---------------- node GEMM: T = tanh(A@Wgat+b), l = T.a ---------------------
// mode 0: A = nodeenc ; mode 1: A = H1
extern "C" __global__ void __launch_bounds__(256,2)
k_tnode(const float* __restrict__ W_gat, const float* __restrict__ b_gat,
        const float* __restrict__ a_gat, int mode) {
    extern __shared__ float sm[];
    float* W_s = sm;
    float* A_s = sm + 16384;
    float* red = sm + 24576;
    const float* A = mode ? g_hn1 : g_nodeenc;
    const int tid = threadIdx.x;
    const int r0 = blockIdx.x*64;
    for (int i = tid; i < 16384; i += 256) W_s[i] = W_gat[i];
    for (int i = tid; i < 8192;  i += 256) A_s[i] = A[(size_t)r0*128 + i];
    __syncthreads();
    const int c8 = (tid & 15)*8, r4 = (tid >> 4)*4;
    float acc[4][8];
#pragma unroll
    for (int i = 0; i < 4; i++)
#pragma unroll
        for (int j = 0; j < 8; j++) acc[i][j] = b_gat[c8+j];
    mm_acc128(A_s, W_s, r4, c8, acc);
#pragma unroll
    for (int i = 0; i < 4; i++) {
        float p = 0.f;
#pragma unroll
        for (int j = 0; j < 8; j++) {
            acc[i][j] = tanhf(acc[i][j]);
            p += acc[i][j]*a_gat[c8+j];
        }
        size_t base = (size_t)(r0+r4+i)*128 + c8;
        *(float4*)(g_tnode + base)   = make_float4(acc[i][0],acc[i][1],acc[i][2],acc[i][3]);
        *(float4*)(g_tnode + base+4) = make_float4(acc[i][4],acc[i][5],acc[i][6],acc[i][7]);
        red[(r4+i)*16 + (tid & 15)] = p;
    }
    __syncthreads();
    if (tid < 64) {
        float s = 0.f;
#pragma unroll
        for (int c = 0; c < 16; c++) s += red[tid*16 + c];
        g_lnode[r0 + tid] = s;
    }
}

// ---------------- node GEMM 128x384 ------------------------------------------
// mode 0: A=xnode -> g_gx ; mode 1: A=nodeenc -> g_gh ; mode 2: A=H1 -> g_gh
extern "C" __global__ void __launch_bounds__(256,2)
k_ngemm384(const float* __restrict__ W, int mode) {
    extern __shared__ float sm[];
    float* W_s = sm;
    float* A_s = sm + 16384;
    const float* A = (mode == 0) ? g_xnode : (mode == 1 ? g_nodeenc : g_hn1);
    float* out     = (mode == 0) ? g_gx    : g_gh;
    const int tid = threadIdx.x;
    const int r0 = blockIdx.x*64;
    const int g  = blockIdx.y;
    for (int i = tid; i < 16384; i += 256) {
        int k = i >> 7, c = i & 127;
        W_s[i] = W[k*384 + g*128 + c];
    }
    for (int i = tid; i < 8192; i += 256) A_s[i] = A[(size_t)r0*128 + i];
    __syncthreads();
    const int c8 = (tid & 15)*8, r4 = (tid >> 4)*4;
    float acc[4][8];
#pragma unroll
    for (int i = 0; i < 4; i++)
#pragma unroll
        for (int j = 0; j < 8; j++) acc[i][j] = 0.f;
    mm_acc128(A_s, W_s, r4, c8, acc);
#pragma unroll
    for (int i = 0; i < 4; i++) {
        size_t base = (size_t)(r0+r4+i)*384 + g*128 + c8;
        *(float4*)(out + base)   = make_float4(acc[i][0],acc[i][1],acc[i][2],acc[i][3]);
        *(float4*)(out + base+4) = make_float4(acc[i][4],acc[i][5],acc[i][6],acc[i][7]);
    }
}

// ---------------- per-node attention + x  (both layers) ----------------------
extern "C" __global__ void k_attn(const int* __restrict__ adj,
                                  const int* __restrict__ num_nodes,
                                  const float* __restrict__ b_gat,
                                  const float* __restrict__ a_gat, int layer) {
    int n = blockIdx.x;
    int t = threadIdx.x;       // 128
    int b = n >> 10;
    __shared__ float red[128];
    __shared__ float at[16];
    __shared__ int   adjs[16];
    __shared__ float vals[16];
    float tb;
    if (layer == 0) {
        tb = tanhf(b_gat[t]);
        red[t] = tb * a_gat[t];
    } else {
        tb = g_tpad[t];
    }
    if (t < 16) {
        int a = adj[n*16 + t];
        vals[t] = (a == num_nodes[b]) ? 0.f : 1.f;
        adjs[t] = b*NV + min(a, NV-1);
    }
    __syncthreads();
    if (layer == 0) {
        for (int s = 64; s > 0; s >>= 1) { if (t < s) red[t] += red[t+s]; __syncthreads(); }
    }
    if (t == 0) {
        float lpadv = (layer == 0) ? red[0] : g_lpad[0];
        float base = lpadv - BIGF;
        float lg[16]; float mx = -1e30f;
#pragma unroll
        for (int d = 0; d < 16; d++) {
            lg[d] = (vals[d] != 0.f) ? g_lnode[adjs[d]] : base;
            mx = fmaxf(mx, lg[d]);
        }
        float ssum = 0.f;
#pragma unroll
        for (int d = 0; d < 16; d++) { lg[d] = expf(lg[d]-mx); ssum += lg[d]; }
        float inv = 1.f/ssum;
#pragma unroll
        for (int d = 0; d < 16; d++) at[d] = lg[d]*inv;
    }
    __syncthreads();
    float msg = 0.f;
#pragma unroll
    for (int d = 0; d < 16; d++) {
        float tv = (vals[d] != 0.f) ? g_tnode[(size_t)adjs[d]*128 + t] : tb;
        msg += at[d]*tv;
    }
    g_xnode[(size_t)n*128 + t] = tanhf(msg + g_nodeenc[(size_t)n*128 + t]);
}

// ---------------- node-level GRU combine --------------------------------------
// mode 0: hprev=nodeenc -> H1 ; mode 1: hprev=H1 -> H2
extern "C" __global__ void k_combnode(const float* __restrict__ bg, int mode) {
    int n   = blockIdx.x*2 + (threadIdx.x >> 7);
    int c   = threadIdx.x & 127;
    const float* hprev = mode ? g_hn1 : g_nodeenc;
    float* out         = mode ? g_hn2 : g_hn1;
    size_t i = (size_t)n*384;
    float gxz = g_gx[i + c],       ghz = g_gh[i + c];
    float gxr = g_gx[i + 128 + c], ghr = g_gh[i + 128 + c];
    float gxc = g_gx[i + 256 + c], ghc = g_gh[i + 256 + c];
    float hp  = hprev[(size_t)n*128 + c];
    float z = sigmoidf_(gxz + ghz + bg[c]);
    float r = sigmoidf_(gxr + ghr + bg[128 + c]);
    float cand = tanhf(gxc + bg[256 + c] + r*ghc);
    out[(size_t)n*128 + c] = z*hp + (1.f - z)*cand;
}

// ---------------- decoder node GEMM: UW = H2 @ wcomb --------------------------
extern "C" __global__ void __launch_bounds__(256,2)
k_udec() {
    extern __shared__ float sm[];
    float* W_s = sm;
    float* A_s = sm + 16384;
    const int tid = threadIdx.x;
    const int r0 = blockIdx.x*64;
    for (int i = tid; i < 16384; i += 256) W_s[i] = g_wcomb[i];
    for (int i = tid; i < 8192;  i += 256) A_s[i] = g_hn2[(size_t)r0*128 + i];
    __syncthreads();
    const int c8 = (tid & 15)*8, r4 = (tid >> 4)*4;
    float acc[4][8];
#pragma unroll
    for (int i = 0; i < 4; i++)
#pragma unroll
        for (int j = 0; j < 8; j++) acc[i][j] = 0.f;
    mm_acc128(A_s, W_s, r4, c8, acc);
#pragma unroll
    for (int i = 0; i < 4; i++) {
        size_t base = (size_t)(r0+r4+i)*128 + c8;
        *(float4*)(g_uwn + base)   = make_float4(acc[i][0],acc[i][1],acc[i][2],acc[i][3]);
        *(float4*)(g_uwn + base+4) = make_float4(acc[i][4],acc[i][5],acc[i][6],acc[i][7]);
    }
}

// ---------------- per-edge nw (warp per edge) ---------------------------------
extern "C" __global__ void k_nw(const float* __restrict__ b1,
                                const float* __restrict__ W2,
                                const float* __restrict__ b2,
                                const int* __restrict__ adj,
                                const int* __restrict__ num_nodes) {
    int e = blockIdx.x*8 + (threadIdx.x >> 5);
    int lane = threadIdx.x & 31;
    int b = e / VD;
    int d = e & 15;
    int nn = num_nodes[b];
    int a_raw = adj[e];
    int an = min(a_raw, NV-1);
    bool ve = (a_raw != nn);
    int a2_raw = adj[(b*NV + an)*ND + (d ^ 1)];
    int an2 = min(a2_raw, NV-1);
    bool ve2 = (a2_raw != nn);
    const float* rowA = ve  ? (g_uwn + (size_t)(b*NV + an)*NH)        : g_uwpad;
    const float* rowB = ve2 ? (g_uwn + (size_t)(b*NV + an2)*NH + 64)  : (g_uwpad + 64);
    float s = 0.f;
#pragma unroll
    for (int j = lane; j < 64; j += 32) {
        float pre = rowA[j] + rowB[j] + b1[j];
        s += tanhf(pre)*W2[j];
    }
#pragma unroll
    for (int o = 16; o > 0; o >>= 1) s += __shfl_down_sync(0xffffffff, s, o);
    if (lane == 0) g_nw[e] = s + b2[0];
}

// ---------------- destination softmax -----------------------------------------
extern "C" __global__ void k_dest(const int* __restrict__ inv_adj,
                                  const int* __restrict__ num_nodes) {
    int bv = blockIdx.x*128 + threadIdx.x;
    if (bv >= NNODES) return;
    int b = bv >> 10;
    int nn = num_nodes[b];
    float w[16]; float mx = -1e30f;
#pragma unroll
    for (int d = 0; d < 16; d++) {
        int ia = inv_adj[bv*16 + d];
        float m = (ia == nn) ? 1.f : 0.f;
        float val = g_nw[(b*NV + min(ia, NV-1))*ND + d] - BIGF*m;
        w[d] = val; mx = fmaxf(mx, val);
    }
    float s = 0.f;
#pragma unroll
    for (int d = 0; d < 16; d++) { w[d] = expf(w[d]-mx); s += w[d]; }
    float inv = 1.f/s;
#pragma unroll
    for (int d = 0; d < 16; d++) g_dest[bv*16 + d] = w[d]*inv;
}

// ---------------- rev-gather + sparsemax ---------------------------------------
extern "C" __global__ void k_sparse(const int* __restrict__ adj,
                                    const int* __restrict__ num_nodes) {
    int bv = blockIdx.x*128 + threadIdx.x;
    if (bv >= NNODES) return;
    int b = bv >> 10;
    int nn = num_nodes[b];
    float z[16], valid[16];
#pragma unroll
    for (int d = 0; d < 16; d++) {
        int a = adj[bv*16 + d];
        float m = (a == nn) ? 1.f : 0.f;
        valid[d] = 1.f - m;
        z[d] = g_dest[(b*NV + min(a, NV-1))*ND + d] - BIGF*m;
    }
    float zs[16];
    for (int d = 0; d < 16; d++) zs[d] = z[d];
    for (int i = 1; i < 16; i++) {
        float key = zs[i]; int j = i-1;
        while (j >= 0 && zs[j] < key) { zs[j+1] = zs[j]; j--; }
        zs[j+1] = key;
    }
    float csum = 0.f, zck = 0.f; int kz = 1;
    for (int k = 1; k <= 16; k++) {
        csum += zs[k-1];
        if (1.f + (float)k*zs[k-1] > csum) { kz = k; zck = csum; }
    }
    float tau = (zck - 1.f)/(float)kz;
#pragma unroll
    for (int d = 0; d < 16; d++)
        g_norm[bv*16 + d] = fmaxf(z[d] - tau, 0.f) * valid[d];
}

// ---------------- flow iterations ----------------------------------------------
extern "C" __global__ void __launch_bounds__(1024,1)
k_flow(const float* __restrict__ demands, const int* __restrict__ inv_adj) {
    extern __shared__ float sm[];
    float* flow_s = sm;
    float* red    = sm + VD;
    int b = blockIdx.x, v = threadIdx.x;
    int base = (b*NV + v)*ND;
    float nrm[16]; int ia[16];
#pragma unroll
    for (int d = 0; d < 16; d++) {
        nrm[d] = g_norm[base + d];
        ia[d]  = min(inv_adj[base + d], NV-1);
        flow_s[v*16 + d] = 0.f;
    }
    float dem = demands[b*NV + v];
    __syncthreads();
    for (int it = 0; it < 10; it++) {
        float inflow = 0.f;
#pragma unroll
        for (int d = 0; d < 16; d++) inflow += flow_s[ia[d]*16 + d];
        float val = fmaxf(inflow - dem, 0.f);
        __syncthreads();
#pragma unroll
        for (int d = 0; d < 16; d++) flow_s[v*16 + d] = nrm[d]*val;
        __syncthreads();
    }
    float c = 0.f;
#pragma unroll
    for (int d = 0; d < 16; d++) { float f = flow_s[v*16 + d]; c += f*f; }
    red[v] = c; __syncthreads();
    for (int s = 512; s > 0; s >>= 1) { if (v < s) red[v] += red[v+s]; __syncthreads(); }
    if (v == 0) g_flowcost[b] = red[0];
}

// ---------------- dual vars (gathered node_states) -----------------------------
extern "C" __global__ void k_dualvars(const float* __restrict__ W1,
                                      const float* __restrict__ b1,
                                      const float* __restrict__ W2,
                                      const float* __restrict__ b2,
                                      const int* __restrict__ adj,
                                      const int* __restrict__ num_nodes) {
    int bv = blockIdx.x, t = threadIdx.x;  // 128 threads
    int b = bv >> 10;
    __shared__ float ns[128];
    __shared__ float hid[64];
    __shared__ int adjs[16];
    __shared__ float vals[16];
    if (t < 16) {
        int a = adj[bv*16 + t];
        vals[t] = (a == num_nodes[b]) ? 0.f : 1.f;
        adjs[t] = b*NV + min(a, NV-1);
    }
    __syncthreads();
    float hpad = g_h2pad[t];
    float s = 0.f;
#pragma unroll
    for (int d = 0; d < 16; d++)
        s += (vals[d] != 0.f) ? g_hn2[(size_t)adjs[d]*128 + t] : hpad;
    ns[t] = s;
    __syncthreads();
    if (t < 64) {
        float a = b1[t];
        for (int k = 0; k < 128; k++) a += ns[k]*W1[k*NHD + t];
        hid[t] = tanhf(a) * W2[t];
    }
    __syncthreads();
    for (int st = 32; st > 0; st >>= 1) { if (t < st) hid[t] += hid[t+st]; __syncthreads(); }
    if (t == 0) g_dualvars[bv] = fmaxf(hid[0] + b2[0], 0.f);
}

// ---------------- dual flows + output ------------------------------------------
extern "C" __global__ void k_final(const float* __restrict__ demands,
                                   const int* __restrict__ adj,
                                   const int* __restrict__ num_nodes,
                                   float* __restrict__ out) {
    int b = blockIdx.x, tid = threadIdx.x;
    int nn = num_nodes[b];
    __shared__ float red[256];
    float ddem = 0.f;
    for (int v = tid; v < NV; v += 256)
        ddem += g_dualvars[b*NV + v]*demands[b*NV + v];
    float ec = 0.f;
    for (int i = tid; i < VD; i += 256) {
        int v = i >> 4;
        int a = adj[b*VD + i];
        float m = (a == nn) ? 1.f : 0.f;
        float valid = 1.f - m;
        float dvv = g_dualvars[b*NV + v];
        float dual = m*dvv;
        float dtr = g_dualvars[b*NV + min(a, NV-1)]*valid;
        float dd = dtr - dual;
        float f = 0.f, vel = 0.f;
#pragma unroll
        for (int it = 0; it < 10; it++) {
            float grad = 2.f*f + dd;
            vel = 0.9f*vel - 0.01f*grad;
            f = fmaxf(f + vel, 0.f);
        }
        float df = f*valid;
        ec += df*df + dd*df;
    }
    red[tid] = ec - ddem;
    __syncthreads();
    for (int s = 128; s > 0; s >>= 1) { if (tid < s) red[tid] += red[tid+s]; __syncthreads(); }
    if (tid == 0) out[b] = g_flowcost[b] - red[0];
}

#define TNODE_SMEM ((16384+8192+1024)*4)
#define NGEMM_SMEM ((16384+8192)*4)
#define FLOW_SMEM  ((VD+1024)*4)

extern "C" void kernel_launch(void* const* d_in, const int* in_sizes, int n_in,
                              void* d_out, int out_size) {
    const float* demands       = (const float*)d_in[0];
    const float* node_features = (const float*)d_in[1];
    const float* node_emb      = (const float*)d_in[4];
    const float* W_enc   = (const float*)d_in[5];
    const float* b_enc   = (const float*)d_in[6];
    const float* W_gat   = (const float*)d_in[7];
    const float* b_gat   = (const float*)d_in[8];
    const float* a_gat   = (const float*)d_in[9];
    const float* W_gru_x = (const float*)d_in[10];
    const float* W_gru_h = (const float*)d_in[11];
    const float* b_gru   = (const float*)d_in[12];
    const float* W_dec1  = (const float*)d_in[13];
    const float* b_dec1  = (const float*)d_in[14];
    const float* W_dec2  = (const float*)d_in[15];
    const float* b_dec2  = (const float*)d_in[16];
    const float* W_dual1 = (const float*)d_in[17];
    const float* b_dual1 = (const float*)d_in[18];
    const float* W_dual2 = (const float*)d_in[19];
    const float* b_dual2 = (const float*)d_in[20];
    const int* adj       = (const int*)d_in[21];
    const int* inv_adj   = (const int*)d_in[22];
    const int* num_nodes = (const int*)d_in[26];
    float* out = (float*)d_out;

    cudaFuncSetAttribute(k_tnode,    cudaFuncAttributeMaxDynamicSharedMemorySize, TNODE_SMEM);
    cudaFuncSetAttribute(k_ngemm384, cudaFuncAttributeMaxDynamicSharedMemorySize, NGEMM_SMEM);
    cudaFuncSetAttribute(k_udec,     cudaFuncAttributeMaxDynamicSharedMemorySize, NGEMM_SMEM);
    cudaFuncSetAttribute(k_flow,     cudaFuncAttributeMaxDynamicSharedMemorySize, FLOW_SMEM);

    dim3 ng(NNODES/64, 3);

    k_enc0<<<NV, 128>>>(node_emb, W_enc);
    k_nodeenc<<<NNODES, 128>>>(node_features, W_enc, b_enc);
    k_wprep<<<64, 256>>>(W_dec1);
    k_pads<<<1, 128>>>(b_gru, W_gru_h, W_gat, b_gat, a_gat);

    // ---- layer 1 (node-level) ----
    k_tnode<<<NNODES/64, 256, TNODE_SMEM>>>(W_gat, b_gat, a_gat, 0);
    k_attn<<<NNODES, 128>>>(adj, num_nodes, b_gat, a_gat, 0);
    k_ngemm384<<<ng, 256, NGEMM_SMEM>>>(W_gru_h, 1);   // g_gh = nodeenc @ Wh
    k_ngemm384<<<ng, 256, NGEMM_SMEM>>>(W_gru_x, 0);   // g_gx = xnode @ Wx
    k_combnode<<<NNODES/2, 256>>>(b_gru, 0);           // -> H1

    // ---- layer 2 (node-level) ----
    k_tnode<<<NNODES/64, 256, TNODE_SMEM>>>(W_gat, b_gat, a_gat, 1);
    k_attn<<<NNODES, 128>>>(adj, num_nodes, b_gat, a_gat, 1);
    k_ngemm384<<<ng, 256, NGEMM_SMEM>>>(W_gru_h, 2);   // g_gh = H1 @ Wh
    k_ngemm384<<<ng, 256, NGEMM_SMEM>>>(W_gru_x, 0);   // g_gx = xnode2 @ Wx
    k_combnode<<<NNODES/2, 256>>>(b_gru, 1);           // -> H2

    // ---- decoder ----
    k_udec<<<NNODES/64, 256, NGEMM_SMEM>>>();
    k_nw<<<ROWS_TOTAL/8, 256>>>(b_dec1, W_dec2, b_dec2, adj, num_nodes);

    // ---- flow / dual / output ----
    k_dest<<<NNODES/128, 128>>>(inv_adj, num_nodes);
    k_sparse<<<NNODES/128, 128>>>(adj, num_nodes);
    k_flow<<<NB, 1024, FLOW_SMEM>>>(demands, inv_adj);
    k_dualvars<<<NNODES, 128>>>(W_dual1, b_dual1, W_dual2, b_dual2, adj, num_nodes);
    k_final<<<NB, 256>>>(demands, adj, num_nodes, out);
}

// round 4
// speedup vs baseline: 13.3746x; 1.3972x over previous
#include <cuda_runtime.h>
#include <math.h>
#include <stdint.h>

#define NB 16
#define NV 1024
#define ND 16
#define NE 64
#define NF 16
#define NH 128
#define NHD 64
#define BIGF 1e9f
#define VD (NV*ND)
#define ROWS_TOTAL (NB*VD)
#define NNODES (NB*NV)

// ---- node-level scratch -----------------------------------------------------
__device__ float g_nodeenc[NNODES*NH];
__device__ float g_xnode[NNODES*NH];
__device__ float g_tnode[NNODES*NH];
__device__ float g_lnode[NNODES];
__device__ float g_hn1[NNODES*NH];
__device__ float g_hn2[NNODES*NH];
__device__ float g_gx[NNODES*3*NH];
__device__ float g_gh[NNODES*3*NH];
__device__ float g_uwn[NNODES*NH];
__device__ float g_enc0[NV*NH];
__device__ float g_wcomb[NH*NH];
__device__ float g_tpad[NH];
__device__ float g_lpad[1];
__device__ float g_h2pad[NH];
__device__ float g_uwpad[NH];
__device__ float g_nw[ROWS_TOTAL];
__device__ float g_dest[ROWS_TOTAL];
__device__ float g_norm[ROWS_TOTAL];
__device__ float g_dualvars[NNODES];
__device__ float g_flowcost[NB];

__device__ __forceinline__ float sigmoidf_(float x) { return 1.f/(1.f+expf(-x)); }

// ---- tf32 helpers -------------------------------------------------------------
__device__ __forceinline__ uint32_t f2tf(float x) {
    uint32_t r;
    asm("cvt.rna.tf32.f32 %0, %1;" : "=r"(r) : "f"(x));
    return r;
}
__device__ __forceinline__ void mma_tf32(float (&c)[4],
                                         uint32_t a0, uint32_t a1, uint32_t a2, uint32_t a3,
                                         uint32_t b0, uint32_t b1) {
    asm volatile("mma.sync.aligned.m16n8k8.row.col.f32.tf32.tf32.f32 "
                 "{%0,%1,%2,%3},{%4,%5,%6,%7},{%8,%9},{%0,%1,%2,%3};"
                 : "+f"(c[0]), "+f"(c[1]), "+f"(c[2]), "+f"(c[3])
                 : "r"(a0), "r"(a1), "r"(a2), "r"(a3), "r"(b0), "r"(b1));
}

// ================= tensor-core node GEMM (3xTF32) ==============================
// C[16384 x Nc] = A[16384 x 128] @ W[:, colBase:colBase+128]
// block: 256 thr, tile M=64 x N=128; warp tile 32x32 (2x4 m16n8k8)
// asel: 0=nodeenc 1=hn1 2=xnode 3=hn2
// osel: 0=g_gx(384) 1=g_gh(384) 2=g_tnode(+lnode, tanh, bias) 3=g_uwn(W=g_wcomb)
#define TMM_SMEM ((64*132 + 128*132 + 256)*4)
extern "C" __global__ void __launch_bounds__(256,2)
k_tmm(const float* __restrict__ Wg, const float* __restrict__ b_gat,
      const float* __restrict__ a_gat, int asel, int osel) {
    extern __shared__ float sm[];
    float* A_s  = sm;                  // 64*132
    float* Bt_s = sm + 64*132;         // 128*132  ([n][k])
    float* red  = Bt_s + 128*132;      // 64*4
    const float* A = (asel==0) ? g_nodeenc : (asel==1) ? g_hn1 :
                     (asel==2) ? g_xnode   : g_hn2;
    const float* W = (osel==3) ? g_wcomb : Wg;
    const int wstride = (osel<=1) ? 384 : 128;
    const int colBase = blockIdx.y * 128;
    const int r0 = blockIdx.x * 64;
    const int tid = threadIdx.x;

    for (int i = tid; i < 64*128; i += 256) {
        int r = i >> 7, c = i & 127;
        A_s[r*132 + c] = A[(size_t)(r0+r)*128 + c];
    }
    for (int i = tid; i < 128*128; i += 256) {
        int k = i >> 7, n = i & 127;
        Bt_s[n*132 + k] = W[k*wstride + colBase + n];
    }
    __syncthreads();

    const int warp = tid >> 5, lane = tid & 31;
    const int wm = warp & 1, wn = warp >> 1;       // 2 x 4 warps
    const int g = lane >> 2, t4 = lane & 3;

    float c[2][4][4];
#pragma unroll
    for (int mt = 0; mt < 2; mt++)
#pragma unroll
        for (int nt = 0; nt < 4; nt++) {
            if (osel == 2) {
                int col = wn*32 + nt*8 + 2*t4;
                c[mt][nt][0] = b_gat[col];
                c[mt][nt][1] = b_gat[col+1];
                c[mt][nt][2] = b_gat[col];
                c[mt][nt][3] = b_gat[col+1];
            } else {
                c[mt][nt][0]=c[mt][nt][1]=c[mt][nt][2]=c[mt][nt][3]=0.f;
            }
        }

#pragma unroll
    for (int ks = 0; ks < 16; ks++) {
        const int k0 = ks*8;
        uint32_t ah[2][4], al[2][4];
#pragma unroll
        for (int mt = 0; mt < 2; mt++) {
            int rb = wm*32 + mt*16;
            float a0 = A_s[(rb+g  )*132 + k0 + t4];
            float a1 = A_s[(rb+g+8)*132 + k0 + t4];
            float a2 = A_s[(rb+g  )*132 + k0 + t4 + 4];
            float a3 = A_s[(rb+g+8)*132 + k0 + t4 + 4];
            ah[mt][0]=f2tf(a0); al[mt][0]=f2tf(a0-__uint_as_float(ah[mt][0]));
            ah[mt][1]=f2tf(a1); al[mt][1]=f2tf(a1-__uint_as_float(ah[mt][1]));
            ah[mt][2]=f2tf(a2); al[mt][2]=f2tf(a2-__uint_as_float(ah[mt][2]));
            ah[mt][3]=f2tf(a3); al[mt][3]=f2tf(a3-__uint_as_float(ah[mt][3]));
        }
        uint32_t bh[4][2], bl[4][2];
#pragma unroll
        for (int nt = 0; nt < 4; nt++) {
            int cb = wn*32 + nt*8 + g;
            float b0 = Bt_s[cb*132 + k0 + t4];
            float b1 = Bt_s[cb*132 + k0 + t4 + 4];
            bh[nt][0]=f2tf(b0); bl[nt][0]=f2tf(b0-__uint_as_float(bh[nt][0]));
            bh[nt][1]=f2tf(b1); bl[nt][1]=f2tf(b1-__uint_as_float(bh[nt][1]));
        }
#pragma unroll
        for (int mt = 0; mt < 2; mt++)
#pragma unroll
            for (int nt = 0; nt < 4; nt++) {
                mma_tf32(c[mt][nt], ah[mt][0],ah[mt][1],ah[mt][2],ah[mt][3], bh[nt][0],bh[nt][1]);
                mma_tf32(c[mt][nt], ah[mt][0],ah[mt][1],ah[mt][2],ah[mt][3], bl[nt][0],bl[nt][1]);
                mma_tf32(c[mt][nt], al[mt][0],al[mt][1],al[mt][2],al[mt][3], bh[nt][0],bh[nt][1]);
            }
    }

    // ---------------- epilogue ----------------
    if (osel == 2) {
        // tanh + store g_tnode + l-dot
#pragma unroll
        for (int mt = 0; mt < 2; mt++) {
            int rA = wm*32 + mt*16 + g;
            float lsA = 0.f, lsB = 0.f;
#pragma unroll
            for (int nt = 0; nt < 4; nt++) {
                int col = wn*32 + nt*8 + 2*t4;
                float t0 = tanhf(c[mt][nt][0]);
                float t1 = tanhf(c[mt][nt][1]);
                float t2 = tanhf(c[mt][nt][2]);
                float t3 = tanhf(c[mt][nt][3]);
                *(float2*)(g_tnode + (size_t)(r0+rA  )*128 + col) = make_float2(t0,t1);
                *(float2*)(g_tnode + (size_t)(r0+rA+8)*128 + col) = make_float2(t2,t3);
                float a0v = a_gat[col], a1v = a_gat[col+1];
                lsA += t0*a0v + t1*a1v;
                lsB += t2*a0v + t3*a1v;
            }
#pragma unroll
            for (int o = 1; o < 4; o <<= 1) {
                lsA += __shfl_xor_sync(0xffffffff, lsA, o);
                lsB += __shfl_xor_sync(0xffffffff, lsB, o);
            }
            if (t4 == 0) {
                red[rA*4 + wn]     = lsA;
                red[(rA+8)*4 + wn] = lsB;
            }
        }
        __syncthreads();
        if (tid < 64) {
            float l = red[tid*4] + red[tid*4+1] + red[tid*4+2] + red[tid*4+3];
            g_lnode[r0 + tid] = l;
        }
    } else {
        float* out = (osel==0) ? g_gx : (osel==1) ? g_gh : g_uwn;
        const int ostride = (osel<=1) ? 384 : 128;
#pragma unroll
        for (int mt = 0; mt < 2; mt++) {
            int rA = r0 + wm*32 + mt*16 + g;
#pragma unroll
            for (int nt = 0; nt < 4; nt++) {
                int col = colBase + wn*32 + nt*8 + 2*t4;
                *(float2*)(out + (size_t)rA*ostride + col)     = make_float2(c[mt][nt][0], c[mt][nt][1]);
                *(float2*)(out + (size_t)(rA+8)*ostride + col) = make_float2(c[mt][nt][2], c[mt][nt][3]);
            }
        }
    }
}

// ---------------- encoding -----------------------------------------------------
extern "C" __global__ void k_enc0(const float* __restrict__ emb,
                                  const float* __restrict__ W_enc) {
    int v = blockIdx.x, t = threadIdx.x;
    __shared__ float e_s[NE];
    __shared__ float red[128];
    if (t < NE) e_s[t] = emb[v*NE + t];
    __syncthreads();
    float sq = (t < NE) ? e_s[t]*e_s[t] : 0.f;
    red[t] = sq; __syncthreads();
    for (int s = 64; s > 0; s >>= 1) { if (t < s) red[t] += red[t+s]; __syncthreads(); }
    float inv = 1.f / fmaxf(sqrtf(red[0]), 1.f);
    float acc = 0.f;
    for (int k = 0; k < NE; k++) acc += e_s[k]*inv*W_enc[k*NH + t];
    g_enc0[v*NH + t] = acc;
}

extern "C" __global__ void k_nodeenc(const float* __restrict__ nf,
                                     const float* __restrict__ W_enc,
                                     const float* __restrict__ b_enc) {
    int bv = blockIdx.x, t = threadIdx.x;
    int v = bv % NV;
    __shared__ float f_s[NF];
    if (t < NF) f_s[t] = nf[bv*NF + t];
    __syncthreads();
    float acc = g_enc0[v*NH + t] + b_enc[t];
    for (int k = 0; k < NF; k++) acc += f_s[k]*W_enc[(NE+k)*NH + t];
    g_nodeenc[bv*NH + t] = acc;
}

extern "C" __global__ void k_wprep(const float* __restrict__ W1) {
    int t = blockIdx.x*256 + threadIdx.x;
    int k = t >> 7, c = t & 127;
    float v;
    if (c < 64) v = W1[k*64 + c] + W1[(128+k)*64 + c];
    else        v = W1[(128+k)*64 + (c-64)];
    g_wcomb[t] = v;
}

// ---------------- pads (parallel, 512 threads) ----------------------------------
extern "C" __global__ void k_pads(const float* __restrict__ bg,
                                  const float* __restrict__ Wh,
                                  const float* __restrict__ W_gat,
                                  const float* __restrict__ b_gat,
                                  const float* __restrict__ a_gat) {
    int t = threadIdx.x;  // 512
    __shared__ float h1p[128], ghp[384], red[128], h2ps[128];
    if (t < 128) h1p[t] = (1.f - sigmoidf_(bg[t])) * tanhf(bg[256+t]);
    __syncthreads();
    if (t < 384) {
        float s = 0.f;
        for (int k = 0; k < 128; k++) s += h1p[k]*Wh[k*384 + t];
        ghp[t] = s;
    } else {
        int c = t - 384;
        float s = b_gat[c];
        for (int k = 0; k < 128; k++) s += h1p[k]*W_gat[k*128 + c];
        float t2 = tanhf(s);
        g_tpad[c] = t2;
        red[c] = t2*a_gat[c];
    }
    __syncthreads();
    for (int st = 64; st > 0; st >>= 1) { if (t < st) red[t] += red[t+st]; __syncthreads(); }
    if (t == 0) g_lpad[0] = red[0];
    if (t < 128) {
        float z = sigmoidf_(bg[t] + ghp[t]);
        float r = sigmoidf_(bg[128+t] + ghp[128+t]);
        float cand = tanhf(bg[256+t] + r*ghp[256+t]);
        float h2p = z*h1p[t] + (1.f - z)*cand;
        g_h2pad[t] = h2p;
        h2ps[t] = h2p;
    }
    __syncthreads();
    if (t < 128) {
        float u = 0.f;
        for (int k = 0; k < 128; k++) u += h2ps[k]*g_wcomb[k*128 + t];
        g_uwpad[t] = u;
    }
}

// ---------------- per-node attention + x ----------------------------------------
extern "C" __global__ void k_attn(const int* __restrict__ adj,
                                  const int* __restrict__ num_nodes,
                                  const float* __restrict__ b_gat,
                                  const float* __restrict__ a_gat, int layer) {
    int n = blockIdx.x;
    int t = threadIdx.x;       // 128
    int b = n >> 10;
    __shared__ float red[128];
    __shared__ float at[16];
    __shared__ int   adjs[16];
    __shared__ float vals[16];
    float tb;
    if (layer == 0) {
        tb = tanhf(b_gat[t]);
        red[t] = tb * a_gat[t];
    } else {
        tb = g_tpad[t];
    }
    if (t < 16) {
        int a = adj[n*16 + t];
        vals[t] = (a == num_nodes[b]) ? 0.f : 1.f;
        adjs[t] = b*NV + min(a, NV-1);
    }
    __syncthreads();
    if (layer == 0) {
        for (int s = 64; s > 0; s >>= 1) { if (t < s) red[t] += red[t+s]; __syncthreads(); }
    }
    if (t == 0) {
        float lpadv = (layer == 0) ? red[0] : g_lpad[0];
        float base = lpadv - BIGF;
        float lg[16]; float mx = -1e30f;
#pragma unroll
        for (int d = 0; d < 16; d++) {
            lg[d] = (vals[d] != 0.f) ? g_lnode[adjs[d]] : base;
            mx = fmaxf(mx, lg[d]);
        }
        float ssum = 0.f;
#pragma unroll
        for (int d = 0; d < 16; d++) { lg[d] = expf(lg[d]-mx); ssum += lg[d]; }
        float inv = 1.f/ssum;
#pragma unroll
        for (int d = 0; d < 16; d++) at[d] = lg[d]*inv;
    }
    __syncthreads();
    float msg = 0.f;
#pragma unroll
    for (int d = 0; d < 16; d++) {
        float tv = (vals[d] != 0.f) ? g_tnode[(size_t)adjs[d]*128 + t] : tb;
        msg += at[d]*tv;
    }
    g_xnode[(size_t)n*128 + t] = tanhf(msg + g_nodeenc[(size_t)n*128 + t]);
}

// ---------------- node-level GRU combine -----------------------------------------
extern "C" __global__ void k_combnode(const float* __restrict__ bg, int mode) {
    int n   = blockIdx.x*2 + (threadIdx.x >> 7);
    int c   = threadIdx.x & 127;
    const float* hprev = mode ? g_hn1 : g_nodeenc;
    float* out         = mode ? g_hn2 : g_hn1;
    size_t i = (size_t)n*384;
    float gxz = g_gx[i + c],       ghz = g_gh[i + c];
    float gxr = g_gx[i + 128 + c], ghr = g_gh[i + 128 + c];
    float gxc = g_gx[i + 256 + c], ghc = g_gh[i + 256 + c];
    float hp  = hprev[(size_t)n*128 + c];
    float z = sigmoidf_(gxz + ghz + bg[c]);
    float r = sigmoidf_(gxr + ghr + bg[128 + c]);
    float cand = tanhf(gxc + bg[256 + c] + r*ghc);
    out[(size_t)n*128 + c] = z*hp + (1.f - z)*cand;
}

// ---------------- per-edge nw ------------------------------------------------------
extern "C" __global__ void k_nw(const float* __restrict__ b1,
                                const float* __restrict__ W2,
                                const float* __restrict__ b2,
                                const int* __restrict__ adj,
                                const int* __restrict__ num_nodes) {
    int e = blockIdx.x*8 + (threadIdx.x >> 5);
    int lane = threadIdx.x & 31;
    int b = e / VD;
    int d = e & 15;
    int nn = num_nodes[b];
    int a_raw = adj[e];
    int an = min(a_raw, NV-1);
    bool ve = (a_raw != nn);
    int a2_raw = adj[(b*NV + an)*ND + (d ^ 1)];
    int an2 = min(a2_raw, NV-1);
    bool ve2 = (a2_raw != nn);
    const float* rowA = ve  ? (g_uwn + (size_t)(b*NV + an)*NH)        : g_uwpad;
    const float* rowB = ve2 ? (g_uwn + (size_t)(b*NV + an2)*NH + 64)  : (g_uwpad + 64);
    float s = 0.f;
#pragma unroll
    for (int j = lane; j < 64; j += 32) {
        float pre = rowA[j] + rowB[j] + b1[j];
        s += tanhf(pre)*W2[j];
    }
#pragma unroll
    for (int o = 16; o > 0; o >>= 1) s += __shfl_down_sync(0xffffffff, s, o);
    if (lane == 0) g_nw[e] = s + b2[0];
}

// ---------------- destination softmax ----------------------------------------------
extern "C" __global__ void k_dest(const int* __restrict__ inv_adj,
                                  const int* __restrict__ num_nodes) {
    int bv = blockIdx.x*128 + threadIdx.x;
    if (bv >= NNODES) return;
    int b = bv >> 10;
    int nn = num_nodes[b];
    float w[16]; float mx = -1e30f;
#pragma unroll
    for (int d = 0; d < 16; d++) {
        int ia = inv_adj[bv*16 + d];
        float m = (ia == nn) ? 1.f : 0.f;
        float val = g_nw[(b*NV + min(ia, NV-1))*ND + d] - BIGF*m;
        w[d] = val; mx = fmaxf(mx, val);
    }
    float s = 0.f;
#pragma unroll
    for (int d = 0; d < 16; d++) { w[d] = expf(w[d]-mx); s += w[d]; }
    float inv = 1.f/s;
#pragma unroll
    for (int d = 0; d < 16; d++) g_dest[bv*16 + d] = w[d]*inv;
}

// ---------------- rev-gather + sparsemax --------------------------------------------
extern "C" __global__ void k_sparse(const int* __restrict__ adj,
                                    const int* __restrict__ num_nodes) {
    int bv = blockIdx.x*128 + threadIdx.x;
    if (bv >= NNODES) return;
    int b = bv >> 10;
    int nn = num_nodes[b];
    float z[16], valid[16];
#pragma unroll
    for (int d = 0; d < 16; d++) {
        int a = adj[bv*16 + d];
        float m = (a == nn) ? 1.f : 0.f;
        valid[d] = 1.f - m;
        z[d] = g_dest[(b*NV + min(a, NV-1))*ND + d] - BIGF*m;
    }
    float zs[16];
    for (int d = 0; d < 16; d++) zs[d] = z[d];
    for (int i = 1; i < 16; i++) {
        float key = zs[i]; int j = i-1;
        while (j >= 0 && zs[j] < key) { zs[j+1] = zs[j]; j--; }
        zs[j+1] = key;
    }
    float csum = 0.f, zck = 0.f; int kz = 1;
    for (int k = 1; k <= 16; k++) {
        csum += zs[k-1];
        if (1.f + (float)k*zs[k-1] > csum) { kz = k; zck = csum; }
    }
    float tau = (zck - 1.f)/(float)kz;
#pragma unroll
    for (int d = 0; d < 16; d++)
        g_norm[bv*16 + d] = fmaxf(z[d] - tau, 0.f) * valid[d];
}

// ---------------- flow iterations ([d][v] smem, conflict-free) ----------------------
extern "C" __global__ void __launch_bounds__(1024,1)
k_flow(const float* __restrict__ demands, const int* __restrict__ inv_adj) {
    extern __shared__ float sm[];
    float* flow_s = sm;            // [16][1024]
    float* red    = sm + VD;       // 1024
    int b = blockIdx.x, v = threadIdx.x;
    int base = (b*NV + v)*ND;
    float nrm[16]; int ia[16];
#pragma unroll
    for (int d = 0; d < 16; d++) {
        nrm[d] = g_norm[base + d];
        ia[d]  = min(inv_adj[base + d], NV-1);
        flow_s[d*NV + v] = 0.f;
    }
    float dem = demands[b*NV + v];
    __syncthreads();
    for (int it = 0; it < 10; it++) {
        float inflow = 0.f;
#pragma unroll
        for (int d = 0; d < 16; d++) inflow += flow_s[d*NV + ia[d]];
        float val = fmaxf(inflow - dem, 0.f);
        __syncthreads();
#pragma unroll
        for (int d = 0; d < 16; d++) flow_s[d*NV + v] = nrm[d]*val;
        __syncthreads();
    }
    float c = 0.f;
#pragma unroll
    for (int d = 0; d < 16; d++) { float f = flow_s[d*NV + v]; c += f*f; }
    red[v] = c; __syncthreads();
    for (int s = 512; s > 0; s >>= 1) { if (v < s) red[v] += red[v+s]; __syncthreads(); }
    if (v == 0) g_flowcost[b] = red[0];
}

// ---------------- dual vars -----------------------------------------------------------
extern "C" __global__ void k_dualvars(const float* __restrict__ W1,
                                      const float* __restrict__ b1,
                                      const float* __restrict__ W2,
                                      const float* __restrict__ b2,
                                      const int* __restrict__ adj,
                                      const int* __restrict__ num_nodes) {
    int bv = blockIdx.x, t = threadIdx.x;  // 128 threads
    int b = bv >> 10;
    __shared__ float ns[128];
    __shared__ float hid[64];
    __shared__ int adjs[16];
    __shared__ float vals[16];
    if (t < 16) {
        int a = adj[bv*16 + t];
        vals[t] = (a == num_nodes[b]) ? 0.f : 1.f;
        adjs[t] = b*NV + min(a, NV-1);
    }
    __syncthreads();
    float hpad = g_h2pad[t];
    float s = 0.f;
#pragma unroll
    for (int d = 0; d < 16; d++)
        s += (vals[d] != 0.f) ? g_hn2[(size_t)adjs[d]*128 + t] : hpad;
    ns[t] = s;
    __syncthreads();
    if (t < 64) {
        float a = b1[t];
        for (int k = 0; k < 128; k++) a += ns[k]*W1[k*NHD + t];
        hid[t] = tanhf(a) * W2[t];
    }
    __syncthreads();
    for (int st = 32; st > 0; st >>= 1) { if (t < st) hid[t] += hid[t+st]; __syncthreads(); }
    if (t == 0) g_dualvars[bv] = fmaxf(hid[0] + b2[0], 0.f);
}

// ---------------- dual flows + output ---------------------------------------------------
extern "C" __global__ void k_final(const float* __restrict__ demands,
                                   const int* __restrict__ adj,
                                   const int* __restrict__ num_nodes,
                                   float* __restrict__ out) {
    int b = blockIdx.x, tid = threadIdx.x;
    int nn = num_nodes[b];
    __shared__ float red[256];
    float ddem = 0.f;
    for (int v = tid; v < NV; v += 256)
        ddem += g_dualvars[b*NV + v]*demands[b*NV + v];
    float ec = 0.f;
    for (int i = tid; i < VD; i += 256) {
        int v = i >> 4;
        int a = adj[b*VD + i];
        float m = (a == nn) ? 1.f : 0.f;
        float valid = 1.f - m;
        float dvv = g_dualvars[b*NV + v];
        float dual = m*dvv;
        float dtr = g_dualvars[b*NV + min(a, NV-1)]*valid;
        float dd = dtr - dual;
        float f = 0.f, vel = 0.f;
#pragma unroll
        for (int it = 0; it < 10; it++) {
            float grad = 2.f*f + dd;
            vel = 0.9f*vel - 0.01f*grad;
            f = fmaxf(f + vel, 0.f);
        }
        float df = f*valid;
        ec += df*df + dd*df;
    }
    red[tid] = ec - ddem;
    __syncthreads();
    for (int s = 128; s > 0; s >>= 1) { if (tid < s) red[tid] += red[tid+s]; __syncthreads(); }
    if (tid == 0) out[b] = g_flowcost[b] - red[0];
}

#define FLOW_SMEM  ((VD+1024)*4)

extern "C" void kernel_launch(void* const* d_in, const int* in_sizes, int n_in,
                              void* d_out, int out_size) {
    const float* demands       = (const float*)d_in[0];
    const float* node_features = (const float*)d_in[1];
    const float* node_emb      = (const float*)d_in[4];
    const float* W_enc   = (const float*)d_in[5];
    const float* b_enc   = (const float*)d_in[6];
    const float* W_gat   = (const float*)d_in[7];
    const float* b_gat   = (const float*)d_in[8];
    const float* a_gat   = (const float*)d_in[9];
    const float* W_gru_x = (const float*)d_in[10];
    const float* W_gru_h = (const float*)d_in[11];
    const float* b_gru   = (const float*)d_in[12];
    const float* W_dec1  = (const float*)d_in[13];
    const float* b_dec1  = (const float*)d_in[14];
    const float* W_dec2  = (const float*)d_in[15];
    const float* b_dec2  = (const float*)d_in[16];
    const float* W_dual1 = (const float*)d_in[17];
    const float* b_dual1 = (const float*)d_in[18];
    const float* W_dual2 = (const float*)d_in[19];
    const float* b_dual2 = (const float*)d_in[20];
    const int* adj       = (const int*)d_in[21];
    const int* inv_adj   = (const int*)d_in[22];
    const int* num_nodes = (const int*)d_in[26];
    float* out = (float*)d_out;

    cudaFuncSetAttribute(k_tmm,  cudaFuncAttributeMaxDynamicSharedMemorySize, TMM_SMEM);
    cudaFuncSetAttribute(k_flow, cudaFuncAttributeMaxDynamicSharedMemorySize, FLOW_SMEM);

    dim3 ng(NNODES/64, 3);
    dim3 n1(NNODES/64, 1);

    k_enc0<<<NV, 128>>>(node_emb, W_enc);
    k_nodeenc<<<NNODES, 128>>>(node_features, W_enc, b_enc);
    k_wprep<<<64, 256>>>(W_dec1);
    k_pads<<<1, 512>>>(b_gru, W_gru_h, W_gat, b_gat, a_gat);

    // ---- layer 1 ----
    k_tmm<<<n1, 256, TMM_SMEM>>>(W_gat, b_gat, a_gat, 0, 2);   // tnode/lnode from nodeenc
    k_attn<<<NNODES, 128>>>(adj, num_nodes, b_gat, a_gat, 0);
    k_tmm<<<ng, 256, TMM_SMEM>>>(W_gru_h, b_gat, a_gat, 0, 1); // gh = nodeenc @ Wh
    k_tmm<<<ng, 256, TMM_SMEM>>>(W_gru_x, b_gat, a_gat, 2, 0); // gx = xnode @ Wx
    k_combnode<<<NNODES/2, 256>>>(b_gru, 0);                   // -> H1

    // ---- layer 2 ----
    k_tmm<<<n1, 256, TMM_SMEM>>>(W_gat, b_gat, a_gat, 1, 2);   // tnode/lnode from H1
    k_attn<<<NNODES, 128>>>(adj, num_nodes, b_gat, a_gat, 1);
    k_tmm<<<ng, 256, TMM_SMEM>>>(W_gru_h, b_gat, a_gat, 1, 1); // gh = H1 @ Wh
    k_tmm<<<ng, 256, TMM_SMEM>>>(W_gru_x, b_gat, a_gat, 2, 0); // gx = xnode2 @ Wx
    k_combnode<<<NNODES/2, 256>>>(b_gru, 1);                   // -> H2

    // ---- decoder ----
    k_tmm<<<n1, 256, TMM_SMEM>>>(nullptr, b_gat, a_gat, 3, 3); // uwn = H2 @ wcomb
    k_nw<<<ROWS_TOTAL/8, 256>>>(b_dec1, W_dec2, b_dec2, adj, num_nodes);

    // ---- flow / dual / output ----
    k_dest<<<NNODES/128, 128>>>(inv_adj, num_nodes);
    k_sparse<<<NNODES/128, 128>>>(adj, num_nodes);
    k_flow<<<NB, 1024, FLOW_SMEM>>>(demands, inv_adj);
    k_dualvars<<<NNODES, 128>>>(W_dual1, b_dual1, W_dual2, b_dual2, adj, num_nodes);
    k_final<<<NB, 256>>>(demands, adj, num_nodes, out);
}